// round 5
// baseline (speedup 1.0000x reference)
#include <cuda_runtime.h>

#define NN 50000
#define NE 800000
#define SCAN_B 512
#define SCAN_NB ((NN + SCAN_B - 1) / SCAN_B)  // 98

// ---------------------------------------------------------------------------
// Scratch (__device__ globals; float4-typed where vector-accessed)
// ---------------------------------------------------------------------------
__device__ int    g_is64;            // edge_index dtype flag (detected on device)
__device__ float  g_deg[NN];
__device__ float  g_dinv[NN];
__device__ int    g_cnt[NN];
__device__ int    g_off[NN + 1];
__device__ int    g_cursor[NN];
__device__ int    g_bsum[SCAN_NB];
__device__ int    g_bpre[SCAN_NB];
__device__ int    g_src[NE];         // edge sources, sorted by destination
__device__ float  g_coef[NE];        // dinv[row]*w*dinv[col], same order
__device__ float4 g_h4[NN * 32];     // layer activations [NN][128]
__device__ float4 g_m4[NN * 32];     // GEMM output       [NN][128]

// packed f32x2 FMA (ptxas never auto-fuses FFMA2; PTX-only path)
__device__ __forceinline__ unsigned long long fma2(unsigned long long a,
                                                   unsigned long long b,
                                                   unsigned long long c) {
    unsigned long long d;
    asm("fma.rn.f32x2 %0, %1, %2, %3;" : "=l"(d) : "l"(a), "l"(b), "l"(c));
    return d;
}

__device__ __forceinline__ float hsum2(unsigned long long p) {
    float lo, hi;
    asm("mov.b64 {%0, %1}, %2;" : "=f"(lo), "=f"(hi) : "l"(p));
    return lo + hi;
}

// ---------------------------------------------------------------------------
// Fused: zero counters everywhere + dtype detect in block 0.
// int64 data (ids < 2^31) -> every odd int32 word zero; int32 -> random ids.
// ---------------------------------------------------------------------------
__global__ void k_detect_zero(const int* __restrict__ ei32) {
    int i = blockIdx.x * blockDim.x + threadIdx.x;
    if (i < NN) { g_deg[i] = 0.0f; g_cnt[i] = 0; }
    if (blockIdx.x == 0) {
        __shared__ int nz;
        if (threadIdx.x == 0) nz = 0;
        __syncthreads();
        for (int k = threadIdx.x; k < 2048; k += blockDim.x)
            if (ei32[2 * k + 1] != 0) nz = 1;
        __syncthreads();
        if (threadIdx.x == 0) g_is64 = (nz == 0) ? 1 : 0;
    }
}

__device__ __forceinline__ int load_idx(const void* ei, long i) {
    int v = g_is64 ? (int)((const long long*)ei)[i] : ((const int*)ei)[i];
    return min(max(v, 0), NN - 1);  // defensive clamp: wrong-answer beats trap
}

// ---------------------------------------------------------------------------
// Normalization + CSR build
// ---------------------------------------------------------------------------
__global__ void k_deg_count(const void* __restrict__ ei, const float* __restrict__ ew) {
    int e = blockIdx.x * blockDim.x + threadIdx.x;
    if (e < NE) {
        int col = load_idx(ei, (long)NE + e);
        atomicAdd(&g_deg[col], ew[e]);
        atomicAdd(&g_cnt[col], 1);
    }
}

// scan step 1, fused with dinv (deg is final here)
__global__ void k_scan1() {
    __shared__ int s[SCAN_B];
    int tid = threadIdx.x;
    int i = blockIdx.x * SCAN_B + tid;
    if (i < NN) g_dinv[i] = rsqrtf(g_deg[i] + 1.0f);  // self-loop weight 1
    int v = (i < NN) ? g_cnt[i] : 0;
    s[tid] = v;
    __syncthreads();
#pragma unroll
    for (int off = 1; off < SCAN_B; off <<= 1) {
        int t = (tid >= off) ? s[tid - off] : 0;
        __syncthreads();
        s[tid] += t;
        __syncthreads();
    }
    if (i < NN) g_off[i] = s[tid] - v;  // exclusive
    if (tid == SCAN_B - 1) g_bsum[blockIdx.x] = s[tid];
}

__global__ void k_scan2() {
    if (threadIdx.x == 0) {
        int acc = 0;
        for (int b = 0; b < SCAN_NB; b++) { g_bpre[b] = acc; acc += g_bsum[b]; }
    }
}

__global__ void k_scan3() {
    int i = blockIdx.x * blockDim.x + threadIdx.x;
    if (i < NN) {
        int o = g_off[i] + g_bpre[i / SCAN_B];
        g_off[i] = o;
        g_cursor[i] = o;
    }
    if (i == 0) g_off[NN] = NE;
}

__global__ void k_fill(const void* __restrict__ ei, const float* __restrict__ ew) {
    int e = blockIdx.x * blockDim.x + threadIdx.x;
    if (e < NE) {
        int row = load_idx(ei, e);
        int col = load_idx(ei, (long)NE + e);
        int pos = atomicAdd(&g_cursor[col], 1);
        pos = min(max(pos, 0), NE - 1);
        g_src[pos] = row;
        g_coef[pos] = g_dinv[row] * ew[e] * g_dinv[col];
    }
}

// ---------------------------------------------------------------------------
// GEMM: m[i][j] = sum_k hin[i][k] * W[j][k]   (W row-major [D][128])
// 256 threads, 64 rows/block, K chunked by 32. Static smem <= 24 KB.
// Inner loop uses packed fma.rn.f32x2 over k-pairs: operands are k-contiguous
// in smem so the packing is free (reinterpret float4 tile as 2x f32x2).
// acc holds (even-k partial, odd-k partial); horizontal add at the end.
// h-tile loads are warp-uniform -> smem broadcast (1 wavefront), so the
// kernel stays FMA-issue-bound at the doubled MAC rate.
// ---------------------------------------------------------------------------
template <int D, bool FROM_X>
__global__ __launch_bounds__(256) void k_gemm(const float* __restrict__ x,
                                              const float* __restrict__ W) {
    const float* hin = FROM_X ? x : (const float*)g_h4;
    __shared__ alignas(16) float Ws[D * 32];
    __shared__ alignas(16) float hs[64 * 32];

    const int tid = threadIdx.x;
    const int warp = tid >> 5, lane = tid & 31;
    const int row0 = blockIdx.x * 64;
    constexpr int CPL = D / 32;  // cols per lane

    unsigned long long acc[8][CPL];
#pragma unroll
    for (int r = 0; r < 8; r++)
#pragma unroll
        for (int t = 0; t < CPL; t++) acc[r][t] = 0ull;  // (+0.f, +0.f)

    for (int c = 0; c < 4; c++) {  // K chunks of 32
        for (int idx = tid; idx < D * 8; idx += 256) {
            int j = idx >> 3, kk4 = idx & 7;
            float4 v = *(const float4*)(W + j * 128 + c * 32 + kk4 * 4);
            *(float4*)(Ws + j * 32 + ((kk4 ^ (j & 7)) << 2)) = v;
        }
        for (int idx = tid; idx < 512; idx += 256) {
            int r = idx >> 3, kk4 = idx & 7;
            int gr = row0 + r;
            float4 v = (gr < NN) ? *(const float4*)(hin + (long)gr * 128 + c * 32 + kk4 * 4)
                                 : make_float4(0.f, 0.f, 0.f, 0.f);
            *(float4*)(hs + r * 32 + kk4 * 4) = v;
        }
        __syncthreads();

#pragma unroll
        for (int kk4 = 0; kk4 < 8; kk4++) {
            ulonglong2 w2[CPL];
#pragma unroll
            for (int t = 0; t < CPL; t++) {
                int col = lane + 32 * t;
                w2[t] = *(const ulonglong2*)(Ws + col * 32 + ((kk4 ^ (col & 7)) << 2));
            }
#pragma unroll
            for (int r = 0; r < 8; r++) {
                ulonglong2 h2 = *(const ulonglong2*)(hs + (warp * 8 + r) * 32 + kk4 * 4);
#pragma unroll
                for (int t = 0; t < CPL; t++) {
                    acc[r][t] = fma2(h2.x, w2[t].x, acc[r][t]);
                    acc[r][t] = fma2(h2.y, w2[t].y, acc[r][t]);
                }
            }
        }
        __syncthreads();
    }

    float* gm = (float*)g_m4;
#pragma unroll
    for (int r = 0; r < 8; r++) {
        int gr = row0 + warp * 8 + r;
        if (gr < NN) {
#pragma unroll
            for (int t = 0; t < CPL; t++) gm[(long)gr * D + lane + 32 * t] = hsum2(acc[r][t]);
        }
    }
}

// ---------------------------------------------------------------------------
// Gather-reduce per destination node, fused self-loop + bias + ReLU.
// D=128: one warp/node, lane = one float4. No atomics. LTS-bandwidth-bound.
// ---------------------------------------------------------------------------
template <bool TO_OUT>
__global__ __launch_bounds__(256) void k_gather128(const float* __restrict__ b,
                                                   float* __restrict__ outp) {
    int n = (blockIdx.x * blockDim.x + threadIdx.x) >> 5;
    int lane = threadIdx.x & 31;
    if (n >= NN) return;
    int beg = g_off[n], end = g_off[n + 1];
    float dn = g_dinv[n];
    float sl = dn * dn;
    float4 acc = g_m4[n * 32 + lane];
    acc.x *= sl; acc.y *= sl; acc.z *= sl; acc.w *= sl;
#pragma unroll 4
    for (int i = beg; i < end; i++) {
        int s = g_src[i];
        float cf = g_coef[i];
        float4 v = g_m4[s * 32 + lane];
        acc.x += cf * v.x; acc.y += cf * v.y; acc.z += cf * v.z; acc.w += cf * v.w;
    }
    int j = lane * 4;
    acc.x = fmaxf(acc.x + __ldg(b + j + 0), 0.0f);
    acc.y = fmaxf(acc.y + __ldg(b + j + 1), 0.0f);
    acc.z = fmaxf(acc.z + __ldg(b + j + 2), 0.0f);
    acc.w = fmaxf(acc.w + __ldg(b + j + 3), 0.0f);
    if (TO_OUT) ((float4*)outp)[n * 32 + lane] = acc;
    else        g_h4[n * 32 + lane] = acc;
}

// D=64: half-warp per node (16 float4 per row)
template <bool TO_OUT>
__global__ __launch_bounds__(256) void k_gather64(const float* __restrict__ b,
                                                  float* __restrict__ outp) {
    int gw = (blockIdx.x * blockDim.x + threadIdx.x) >> 5;
    int lane = threadIdx.x & 31;
    int n = gw * 2 + (lane >> 4);
    int l = lane & 15;
    if (n >= NN) return;
    int beg = g_off[n], end = g_off[n + 1];
    float dn = g_dinv[n];
    float sl = dn * dn;
    float4 acc = g_m4[n * 16 + l];
    acc.x *= sl; acc.y *= sl; acc.z *= sl; acc.w *= sl;
#pragma unroll 4
    for (int i = beg; i < end; i++) {
        int s = g_src[i];
        float cf = g_coef[i];
        float4 v = g_m4[s * 16 + l];
        acc.x += cf * v.x; acc.y += cf * v.y; acc.z += cf * v.z; acc.w += cf * v.w;
    }
    int j = l * 4;
    acc.x = fmaxf(acc.x + __ldg(b + j + 0), 0.0f);
    acc.y = fmaxf(acc.y + __ldg(b + j + 1), 0.0f);
    acc.z = fmaxf(acc.z + __ldg(b + j + 2), 0.0f);
    acc.w = fmaxf(acc.w + __ldg(b + j + 3), 0.0f);
    if (TO_OUT) ((float4*)outp)[n * 16 + l] = acc;
    else        g_h4[n * 16 + l] = acc;
}

// ---------------------------------------------------------------------------
extern "C" void kernel_launch(void* const* d_in, const int* in_sizes, int n_in,
                              void* d_out, int out_size) {
    const float* x = (const float*)d_in[0];
    const void*  ei = d_in[1];                 // int32 or int64 — detected on device
    const float* ew = (const float*)d_in[2];
    const float* W1 = (const float*)d_in[3];
    const float* b1 = (const float*)d_in[4];
    const float* W2 = (const float*)d_in[5];
    const float* b2 = (const float*)d_in[6];
    const float* W3 = (const float*)d_in[7];
    const float* b3 = (const float*)d_in[8];
    float* out = (float*)d_out;

    const int nB = (NN + 255) / 256;
    const int eB = (NE + 255) / 256;

    // --- dtype detect + normalization + CSR build ---
    k_detect_zero<<<nB, 256>>>((const int*)ei);
    k_deg_count<<<eB, 256>>>(ei, ew);
    k_scan1<<<SCAN_NB, SCAN_B>>>();
    k_scan2<<<1, 32>>>();
    k_scan3<<<nB, 256>>>();
    k_fill<<<eB, 256>>>(ei, ew);

    const int gemm_blocks = (NN + 63) / 64;           // 782
    const int g128_blocks = (NN * 32 + 255) / 256;    // warp per node
    const int g64_blocks  = (NN * 16 + 255) / 256;    // half-warp per node

    // --- layer 1 (128 -> 128) ---
    k_gemm<128, true><<<gemm_blocks, 256>>>(x, W1);
    k_gather128<false><<<g128_blocks, 256>>>(b1, nullptr);

    // --- layer 2 (128 -> 128) ---
    k_gemm<128, false><<<gemm_blocks, 256>>>(nullptr, W2);
    k_gather128<false><<<g128_blocks, 256>>>(b2, nullptr);

    // --- layer 3 (128 -> 64) ---
    k_gemm<64, false><<<gemm_blocks, 256>>>(nullptr, W3);
    k_gather64<true><<<g64_blocks, 256>>>(b3, out);
}

// round 6
// speedup vs baseline: 1.1739x; 1.1739x over previous
#include <cuda_runtime.h>

#define NN 50000
#define NE 800000
#define SCAN_B 512
#define SCAN_NB ((NN + SCAN_B - 1) / SCAN_B)  // 98

// ---------------------------------------------------------------------------
// Scratch (__device__ globals; float4-typed where vector-accessed)
// ---------------------------------------------------------------------------
__device__ int    g_is64;            // edge_index dtype flag (detected on device)
__device__ float  g_deg[NN];
__device__ float  g_dinv[NN];
__device__ int    g_cnt[NN];
__device__ int    g_off[NN + 1];
__device__ int    g_cursor[NN];
__device__ int    g_bsum[SCAN_NB];
__device__ int    g_bpre[SCAN_NB];
__device__ int    g_src[NE];         // edge sources, sorted by destination
__device__ float  g_coef[NE];        // dinv[row]*w*dinv[col], same order
__device__ float4 g_h4[NN * 32];     // layer activations [NN][128]
__device__ float4 g_m4[NN * 32];     // GEMM output       [NN][128]

// ---------------------------------------------------------------------------
// Fused: zero counters everywhere + dtype detect in block 0.
// int64 data (ids < 2^31) -> every odd int32 word zero; int32 -> random ids.
// ---------------------------------------------------------------------------
__global__ void k_detect_zero(const int* __restrict__ ei32) {
    int i = blockIdx.x * blockDim.x + threadIdx.x;
    if (i < NN) { g_deg[i] = 0.0f; g_cnt[i] = 0; }
    if (blockIdx.x == 0) {
        __shared__ int nz;
        if (threadIdx.x == 0) nz = 0;
        __syncthreads();
        for (int k = threadIdx.x; k < 2048; k += blockDim.x)
            if (ei32[2 * k + 1] != 0) nz = 1;
        __syncthreads();
        if (threadIdx.x == 0) g_is64 = (nz == 0) ? 1 : 0;
    }
}

__device__ __forceinline__ int load_idx(const void* ei, long i) {
    int v = g_is64 ? (int)((const long long*)ei)[i] : ((const int*)ei)[i];
    return min(max(v, 0), NN - 1);  // defensive clamp: wrong-answer beats trap
}

// ---------------------------------------------------------------------------
// Normalization + CSR build
// ---------------------------------------------------------------------------
__global__ void k_deg_count(const void* __restrict__ ei, const float* __restrict__ ew) {
    int e = blockIdx.x * blockDim.x + threadIdx.x;
    if (e < NE) {
        int col = load_idx(ei, (long)NE + e);
        atomicAdd(&g_deg[col], ew[e]);
        atomicAdd(&g_cnt[col], 1);
    }
}

// scan step 1, fused with dinv (deg is final here)
__global__ void k_scan1() {
    __shared__ int s[SCAN_B];
    int tid = threadIdx.x;
    int i = blockIdx.x * SCAN_B + tid;
    if (i < NN) g_dinv[i] = rsqrtf(g_deg[i] + 1.0f);  // self-loop weight 1
    int v = (i < NN) ? g_cnt[i] : 0;
    s[tid] = v;
    __syncthreads();
#pragma unroll
    for (int off = 1; off < SCAN_B; off <<= 1) {
        int t = (tid >= off) ? s[tid - off] : 0;
        __syncthreads();
        s[tid] += t;
        __syncthreads();
    }
    if (i < NN) g_off[i] = s[tid] - v;  // exclusive
    if (tid == SCAN_B - 1) g_bsum[blockIdx.x] = s[tid];
}

// parallel scan over the 98 block sums (was 8.9us single-threaded)
__global__ void k_scan2() {
    __shared__ int s[128];
    int tid = threadIdx.x;
    int v = (tid < SCAN_NB) ? g_bsum[tid] : 0;
    s[tid] = v;
    __syncthreads();
#pragma unroll
    for (int off = 1; off < 128; off <<= 1) {
        int t = (tid >= off) ? s[tid - off] : 0;
        __syncthreads();
        s[tid] += t;
        __syncthreads();
    }
    if (tid < SCAN_NB) g_bpre[tid] = s[tid] - v;  // exclusive
}

__global__ void k_scan3() {
    int i = blockIdx.x * blockDim.x + threadIdx.x;
    if (i < NN) {
        int o = g_off[i] + g_bpre[i / SCAN_B];
        g_off[i] = o;
        g_cursor[i] = o;
    }
    if (i == 0) g_off[NN] = NE;
}

__global__ void k_fill(const void* __restrict__ ei, const float* __restrict__ ew) {
    int e = blockIdx.x * blockDim.x + threadIdx.x;
    if (e < NE) {
        int row = load_idx(ei, e);
        int col = load_idx(ei, (long)NE + e);
        int pos = atomicAdd(&g_cursor[col], 1);
        pos = min(max(pos, 0), NE - 1);
        g_src[pos] = row;
        g_coef[pos] = g_dinv[row] * ew[e] * g_dinv[col];
    }
}

// ---------------------------------------------------------------------------
// GEMM: m[i][j] = sum_k hin[i][k] * W[j][k]   (W row-major [D][128])
// 256 threads, 64 rows/block, K chunked by 32. Static smem <= 24 KB.
// Warp owns 8 rows; lane owns cols {lane, lane+32, ...}. K vectorized by 4.
// W tile stored [col][32] with kk4 XOR-swizzle -> conflict-free LDS.128.
// (R4-proven scalar-FFMA inner loop; FFMA2 regressed due to RF banking rt=3.)
// ---------------------------------------------------------------------------
template <int D, bool FROM_X>
__global__ __launch_bounds__(256) void k_gemm(const float* __restrict__ x,
                                              const float* __restrict__ W) {
    const float* hin = FROM_X ? x : (const float*)g_h4;
    __shared__ alignas(16) float Ws[D * 32];
    __shared__ alignas(16) float hs[64 * 32];

    const int tid = threadIdx.x;
    const int warp = tid >> 5, lane = tid & 31;
    const int row0 = blockIdx.x * 64;
    constexpr int CPL = D / 32;  // cols per lane

    float acc[8][CPL];
#pragma unroll
    for (int r = 0; r < 8; r++)
#pragma unroll
        for (int t = 0; t < CPL; t++) acc[r][t] = 0.0f;

    for (int c = 0; c < 4; c++) {  // K chunks of 32
        for (int idx = tid; idx < D * 8; idx += 256) {
            int j = idx >> 3, kk4 = idx & 7;
            float4 v = *(const float4*)(W + j * 128 + c * 32 + kk4 * 4);
            *(float4*)(Ws + j * 32 + ((kk4 ^ (j & 7)) << 2)) = v;
        }
        for (int idx = tid; idx < 512; idx += 256) {
            int r = idx >> 3, kk4 = idx & 7;
            int gr = row0 + r;
            float4 v = (gr < NN) ? *(const float4*)(hin + (long)gr * 128 + c * 32 + kk4 * 4)
                                 : make_float4(0.f, 0.f, 0.f, 0.f);
            *(float4*)(hs + r * 32 + kk4 * 4) = v;
        }
        __syncthreads();

#pragma unroll
        for (int kk4 = 0; kk4 < 8; kk4++) {
            float4 w4[CPL];
#pragma unroll
            for (int t = 0; t < CPL; t++) {
                int col = lane + 32 * t;
                w4[t] = *(const float4*)(Ws + col * 32 + ((kk4 ^ (col & 7)) << 2));
            }
#pragma unroll
            for (int r = 0; r < 8; r++) {
                float4 h4 = *(const float4*)(hs + (warp * 8 + r) * 32 + kk4 * 4);
#pragma unroll
                for (int t = 0; t < CPL; t++) {
                    acc[r][t] += h4.x * w4[t].x;
                    acc[r][t] += h4.y * w4[t].y;
                    acc[r][t] += h4.z * w4[t].z;
                    acc[r][t] += h4.w * w4[t].w;
                }
            }
        }
        __syncthreads();
    }

    float* gm = (float*)g_m4;
#pragma unroll
    for (int r = 0; r < 8; r++) {
        int gr = row0 + warp * 8 + r;
        if (gr < NN) {
#pragma unroll
            for (int t = 0; t < CPL; t++) gm[(long)gr * D + lane + 32 * t] = acc[r][t];
        }
    }
}

// ---------------------------------------------------------------------------
// Gather-reduce per destination node, fused self-loop + bias + ReLU.
// D=128: one warp/node, lane = one float4. No atomics. LTS-bandwidth-bound.
// ---------------------------------------------------------------------------
template <bool TO_OUT>
__global__ __launch_bounds__(256) void k_gather128(const float* __restrict__ b,
                                                   float* __restrict__ outp) {
    int n = (blockIdx.x * blockDim.x + threadIdx.x) >> 5;
    int lane = threadIdx.x & 31;
    if (n >= NN) return;
    int beg = g_off[n], end = g_off[n + 1];
    float dn = g_dinv[n];
    float sl = dn * dn;
    float4 acc = g_m4[n * 32 + lane];
    acc.x *= sl; acc.y *= sl; acc.z *= sl; acc.w *= sl;
#pragma unroll 4
    for (int i = beg; i < end; i++) {
        int s = g_src[i];
        float cf = g_coef[i];
        float4 v = g_m4[s * 32 + lane];
        acc.x += cf * v.x; acc.y += cf * v.y; acc.z += cf * v.z; acc.w += cf * v.w;
    }
    int j = lane * 4;
    acc.x = fmaxf(acc.x + __ldg(b + j + 0), 0.0f);
    acc.y = fmaxf(acc.y + __ldg(b + j + 1), 0.0f);
    acc.z = fmaxf(acc.z + __ldg(b + j + 2), 0.0f);
    acc.w = fmaxf(acc.w + __ldg(b + j + 3), 0.0f);
    if (TO_OUT) ((float4*)outp)[n * 32 + lane] = acc;
    else        g_h4[n * 32 + lane] = acc;
}

// D=64: half-warp per node (16 float4 per row)
template <bool TO_OUT>
__global__ __launch_bounds__(256) void k_gather64(const float* __restrict__ b,
                                                  float* __restrict__ outp) {
    int gw = (blockIdx.x * blockDim.x + threadIdx.x) >> 5;
    int lane = threadIdx.x & 31;
    int n = gw * 2 + (lane >> 4);
    int l = lane & 15;
    if (n >= NN) return;
    int beg = g_off[n], end = g_off[n + 1];
    float dn = g_dinv[n];
    float sl = dn * dn;
    float4 acc = g_m4[n * 16 + l];
    acc.x *= sl; acc.y *= sl; acc.z *= sl; acc.w *= sl;
#pragma unroll 4
    for (int i = beg; i < end; i++) {
        int s = g_src[i];
        float cf = g_coef[i];
        float4 v = g_m4[s * 16 + l];
        acc.x += cf * v.x; acc.y += cf * v.y; acc.z += cf * v.z; acc.w += cf * v.w;
    }
    int j = l * 4;
    acc.x = fmaxf(acc.x + __ldg(b + j + 0), 0.0f);
    acc.y = fmaxf(acc.y + __ldg(b + j + 1), 0.0f);
    acc.z = fmaxf(acc.z + __ldg(b + j + 2), 0.0f);
    acc.w = fmaxf(acc.w + __ldg(b + j + 3), 0.0f);
    if (TO_OUT) ((float4*)outp)[n * 16 + l] = acc;
    else        g_h4[n * 16 + l] = acc;
}

// ---------------------------------------------------------------------------
extern "C" void kernel_launch(void* const* d_in, const int* in_sizes, int n_in,
                              void* d_out, int out_size) {
    const float* x = (const float*)d_in[0];
    const void*  ei = d_in[1];                 // int32 or int64 — detected on device
    const float* ew = (const float*)d_in[2];
    const float* W1 = (const float*)d_in[3];
    const float* b1 = (const float*)d_in[4];
    const float* W2 = (const float*)d_in[5];
    const float* b2 = (const float*)d_in[6];
    const float* W3 = (const float*)d_in[7];
    const float* b3 = (const float*)d_in[8];
    float* out = (float*)d_out;

    const int nB = (NN + 255) / 256;
    const int eB = (NE + 255) / 256;

    // --- dtype detect + normalization + CSR build ---
    k_detect_zero<<<nB, 256>>>((const int*)ei);
    k_deg_count<<<eB, 256>>>(ei, ew);
    k_scan1<<<SCAN_NB, SCAN_B>>>();
    k_scan2<<<1, 128>>>();
    k_scan3<<<nB, 256>>>();
    k_fill<<<eB, 256>>>(ei, ew);

    const int gemm_blocks = (NN + 63) / 64;           // 782
    const int g128_blocks = (NN * 32 + 255) / 256;    // warp per node
    const int g64_blocks  = (NN * 16 + 255) / 256;    // half-warp per node

    // --- layer 1 (128 -> 128) ---
    k_gemm<128, true><<<gemm_blocks, 256>>>(x, W1);
    k_gather128<false><<<g128_blocks, 256>>>(b1, nullptr);

    // --- layer 2 (128 -> 128) ---
    k_gemm<128, false><<<gemm_blocks, 256>>>(nullptr, W2);
    k_gather128<false><<<g128_blocks, 256>>>(b2, nullptr);

    // --- layer 3 (128 -> 64) ---
    k_gemm<64, false><<<gemm_blocks, 256>>>(nullptr, W3);
    k_gather64<true><<<g64_blocks, 256>>>(b3, out);
}

// round 8
// speedup vs baseline: 1.1808x; 1.0059x over previous
#include <cuda_runtime.h>
#include <cuda_fp16.h>
#include <cstdint>

#define NN 50000
#define NE 800000
#define SCAN_B 512
#define SCAN_NB ((NN + SCAN_B - 1) / SCAN_B)  // 98

// ---------------------------------------------------------------------------
// Scratch (__device__ globals)
// ---------------------------------------------------------------------------
__device__ int    g_is64;
__device__ float  g_deg[NN];
__device__ float  g_dinv[NN];
__device__ int    g_cnt[NN];
__device__ int    g_off[NN + 1];
__device__ int    g_cursor[NN];
__device__ int    g_bsum[SCAN_NB];
__device__ int    g_src[NE];
__device__ float  g_coef[NE];
__device__ float4 g_h4[NN * 32];                 // activations [NN][128] fp32
__device__ __align__(16) __half2 g_mh[NN * 64];  // messages m [NN][D] fp16 (D/2 half2 per row)

// ---------------------------------------------------------------------------
// Fused: zero counters + dtype detect (int64 high words all zero) in block 0.
// ---------------------------------------------------------------------------
__global__ void k_detect_zero(const int* __restrict__ ei32) {
    int i = blockIdx.x * blockDim.x + threadIdx.x;
    if (i < NN) { g_deg[i] = 0.0f; g_cnt[i] = 0; }
    if (blockIdx.x == 0) {
        __shared__ int nz;
        if (threadIdx.x == 0) nz = 0;
        __syncthreads();
        for (int k = threadIdx.x; k < 2048; k += blockDim.x)
            if (ei32[2 * k + 1] != 0) nz = 1;
        __syncthreads();
        if (threadIdx.x == 0) g_is64 = (nz == 0) ? 1 : 0;
    }
}

__device__ __forceinline__ int load_idx(const void* ei, long i) {
    int v = g_is64 ? (int)((const long long*)ei)[i] : ((const int*)ei)[i];
    return min(max(v, 0), NN - 1);
}

// ---------------------------------------------------------------------------
// Normalization + CSR build
// ---------------------------------------------------------------------------
__global__ void k_deg_count(const void* __restrict__ ei, const float* __restrict__ ew) {
    int e = blockIdx.x * blockDim.x + threadIdx.x;
    if (e < NE) {
        int col = load_idx(ei, (long)NE + e);
        atomicAdd(&g_deg[col], ew[e]);
        atomicAdd(&g_cnt[col], 1);
    }
}

// scan step 1, fused with dinv (deg is final here)
__global__ void k_scan1() {
    __shared__ int s[SCAN_B];
    int tid = threadIdx.x;
    int i = blockIdx.x * SCAN_B + tid;
    if (i < NN) g_dinv[i] = rsqrtf(g_deg[i] + 1.0f);  // self-loop weight 1
    int v = (i < NN) ? g_cnt[i] : 0;
    s[tid] = v;
    __syncthreads();
#pragma unroll
    for (int off = 1; off < SCAN_B; off <<= 1) {
        int t = (tid >= off) ? s[tid - off] : 0;
        __syncthreads();
        s[tid] += t;
        __syncthreads();
    }
    if (i < NN) g_off[i] = s[tid] - v;  // exclusive within block
    if (tid == SCAN_B - 1) g_bsum[blockIdx.x] = s[tid];
}

// fused scan2+scan3: every block re-scans the 98 block sums locally (cheap),
// then applies the prefix. Saves a kernel launch + global roundtrip.
__global__ void k_scan23() {
    __shared__ int s[128];
    __shared__ int pre[SCAN_NB];
    int tid = threadIdx.x;
    int v = 0;
    if (tid < 128) { v = (tid < SCAN_NB) ? g_bsum[tid] : 0; s[tid] = v; }
    __syncthreads();
#pragma unroll
    for (int off = 1; off < 128; off <<= 1) {
        int t = 0;
        if (tid < 128 && tid >= off) t = s[tid - off];
        __syncthreads();
        if (tid < 128) s[tid] += t;
        __syncthreads();
    }
    if (tid < SCAN_NB) pre[tid] = s[tid] - v;  // exclusive block prefix
    __syncthreads();
    int i = blockIdx.x * blockDim.x + tid;
    if (i < NN) {
        int o = g_off[i] + pre[i / SCAN_B];
        g_off[i] = o;
        g_cursor[i] = o;
    }
    if (i == 0) g_off[NN] = NE;
}

__global__ void k_fill(const void* __restrict__ ei, const float* __restrict__ ew) {
    int e = blockIdx.x * blockDim.x + threadIdx.x;
    if (e < NE) {
        int row = load_idx(ei, e);
        int col = load_idx(ei, (long)NE + e);
        int pos = atomicAdd(&g_cursor[col], 1);
        pos = min(max(pos, 0), NE - 1);
        g_src[pos] = row;
        g_coef[pos] = g_dinv[row] * ew[e] * g_dinv[col];
    }
}

// ---------------------------------------------------------------------------
// GEMM: m[i][j] = sum_k hin[i][k] * W[j][k]   (W row-major [D][128])
// R6-proven scalar-FFMA core (FMA-issue-bound). Epilogue repacks each 32-col
// chunk through the (now free) hs tile and stores m as vectorized half2.
// ---------------------------------------------------------------------------
template <int D, bool FROM_X>
__global__ __launch_bounds__(256) void k_gemm(const float* __restrict__ x,
                                              const float* __restrict__ W) {
    const float* hin = FROM_X ? x : (const float*)g_h4;
    __shared__ alignas(16) float Ws[D * 32];
    __shared__ alignas(16) float hs[64 * 32];

    const int tid = threadIdx.x;
    const int warp = tid >> 5, lane = tid & 31;
    const int row0 = blockIdx.x * 64;
    constexpr int CPL = D / 32;  // cols per lane (strided by 32)

    float acc[8][CPL];
#pragma unroll
    for (int r = 0; r < 8; r++)
#pragma unroll
        for (int t = 0; t < CPL; t++) acc[r][t] = 0.0f;

    for (int c = 0; c < 4; c++) {  // K chunks of 32
        for (int idx = tid; idx < D * 8; idx += 256) {
            int j = idx >> 3, kk4 = idx & 7;
            float4 v = *(const float4*)(W + j * 128 + c * 32 + kk4 * 4);
            *(float4*)(Ws + j * 32 + ((kk4 ^ (j & 7)) << 2)) = v;
        }
        for (int idx = tid; idx < 512; idx += 256) {
            int r = idx >> 3, kk4 = idx & 7;
            int gr = row0 + r;
            float4 v = (gr < NN) ? *(const float4*)(hin + (long)gr * 128 + c * 32 + kk4 * 4)
                                 : make_float4(0.f, 0.f, 0.f, 0.f);
            *(float4*)(hs + r * 32 + kk4 * 4) = v;
        }
        __syncthreads();

#pragma unroll
        for (int kk4 = 0; kk4 < 8; kk4++) {
            float4 w4[CPL];
#pragma unroll
            for (int t = 0; t < CPL; t++) {
                int col = lane + 32 * t;
                w4[t] = *(const float4*)(Ws + col * 32 + ((kk4 ^ (col & 7)) << 2));
            }
#pragma unroll
            for (int r = 0; r < 8; r++) {
                float4 h4 = *(const float4*)(hs + (warp * 8 + r) * 32 + kk4 * 4);
#pragma unroll
                for (int t = 0; t < CPL; t++) {
                    acc[r][t] += h4.x * w4[t].x;
                    acc[r][t] += h4.y * w4[t].y;
                    acc[r][t] += h4.z * w4[t].z;
                    acc[r][t] += h4.w * w4[t].w;
                }
            }
        }
        __syncthreads();
    }

    // Epilogue: per col-chunk t, stage acc cols 32t..32t+31 (contiguous) in hs,
    // then pack adjacent col pairs into half2 and store vectorized.
#pragma unroll
    for (int t = 0; t < CPL; t++) {
#pragma unroll
        for (int r = 0; r < 8; r++) hs[(warp * 8 + r) * 32 + lane] = acc[r][t];
        __syncthreads();
        for (int idx = tid; idx < 1024; idx += 256) {
            int row = idx >> 4, a = idx & 15;
            int gr = row0 + row;
            if (gr < NN) {
                float2 f = *(const float2*)(hs + row * 32 + 2 * a);
                g_mh[(long)gr * (D / 2) + t * 16 + a] = __floats2half2_rn(f.x, f.y);
            }
        }
        __syncthreads();
    }
}

// ---------------------------------------------------------------------------
// Gather-reduce per destination node, fused self-loop + bias + ReLU.
// m rows are fp16 (half the L2 traffic); accumulate fp32. No atomics.
// D=128: one warp/node, lane = 4 cols via one uint2 (2 half2) load.
// ---------------------------------------------------------------------------
template <bool TO_OUT>
__global__ __launch_bounds__(256) void k_gather128(const float* __restrict__ b,
                                                   float* __restrict__ outp) {
    int n = (blockIdx.x * blockDim.x + threadIdx.x) >> 5;
    int lane = threadIdx.x & 31;
    if (n >= NN) return;
    const uint2* mh = (const uint2*)g_mh;  // row = 32 uint2 (128 halfs)
    int beg = g_off[n], end = g_off[n + 1];
    float dn = g_dinv[n];
    float sl = dn * dn;
    float4 acc;
    {
        uint2 raw = mh[(long)n * 32 + lane];
        float2 a0 = __half22float2(*(const __half2*)&raw.x);
        float2 a1 = __half22float2(*(const __half2*)&raw.y);
        acc = make_float4(a0.x * sl, a0.y * sl, a1.x * sl, a1.y * sl);
    }
#pragma unroll 4
    for (int i = beg; i < end; i++) {
        int s = g_src[i];
        float cf = g_coef[i];
        uint2 raw = mh[(long)s * 32 + lane];
        float2 v0 = __half22float2(*(const __half2*)&raw.x);
        float2 v1 = __half22float2(*(const __half2*)&raw.y);
        acc.x += cf * v0.x; acc.y += cf * v0.y;
        acc.z += cf * v1.x; acc.w += cf * v1.y;
    }
    int j = lane * 4;
    acc.x = fmaxf(acc.x + __ldg(b + j + 0), 0.0f);
    acc.y = fmaxf(acc.y + __ldg(b + j + 1), 0.0f);
    acc.z = fmaxf(acc.z + __ldg(b + j + 2), 0.0f);
    acc.w = fmaxf(acc.w + __ldg(b + j + 3), 0.0f);
    if (TO_OUT) ((float4*)outp)[n * 32 + lane] = acc;
    else        g_h4[n * 32 + lane] = acc;
}

// D=64: half-warp per node (row = 16 uint2)
template <bool TO_OUT>
__global__ __launch_bounds__(256) void k_gather64(const float* __restrict__ b,
                                                  float* __restrict__ outp) {
    int gw = (blockIdx.x * blockDim.x + threadIdx.x) >> 5;
    int lane = threadIdx.x & 31;
    int n = gw * 2 + (lane >> 4);
    int l = lane & 15;
    if (n >= NN) return;
    const uint2* mh = (const uint2*)g_mh;  // row = 16 uint2 (64 halfs)
    int beg = g_off[n], end = g_off[n + 1];
    float dn = g_dinv[n];
    float sl = dn * dn;
    float4 acc;
    {
        uint2 raw = mh[(long)n * 16 + l];
        float2 a0 = __half22float2(*(const __half2*)&raw.x);
        float2 a1 = __half22float2(*(const __half2*)&raw.y);
        acc = make_float4(a0.x * sl, a0.y * sl, a1.x * sl, a1.y * sl);
    }
#pragma unroll 4
    for (int i = beg; i < end; i++) {
        int s = g_src[i];
        float cf = g_coef[i];
        uint2 raw = mh[(long)s * 16 + l];
        float2 v0 = __half22float2(*(const __half2*)&raw.x);
        float2 v1 = __half22float2(*(const __half2*)&raw.y);
        acc.x += cf * v0.x; acc.y += cf * v0.y;
        acc.z += cf * v1.x; acc.w += cf * v1.y;
    }
    int j = l * 4;
    acc.x = fmaxf(acc.x + __ldg(b + j + 0), 0.0f);
    acc.y = fmaxf(acc.y + __ldg(b + j + 1), 0.0f);
    acc.z = fmaxf(acc.z + __ldg(b + j + 2), 0.0f);
    acc.w = fmaxf(acc.w + __ldg(b + j + 3), 0.0f);
    if (TO_OUT) ((float4*)outp)[n * 16 + l] = acc;
    else        g_h4[n * 16 + l] = acc;
}

// ---------------------------------------------------------------------------
extern "C" void kernel_launch(void* const* d_in, const int* in_sizes, int n_in,
                              void* d_out, int out_size) {
    const float* x = (const float*)d_in[0];
    const void*  ei = d_in[1];                 // int32 or int64 — detected on device
    const float* ew = (const float*)d_in[2];
    const float* W1 = (const float*)d_in[3];
    const float* b1 = (const float*)d_in[4];
    const float* W2 = (const float*)d_in[5];
    const float* b2 = (const float*)d_in[6];
    const float* W3 = (const float*)d_in[7];
    const float* b3 = (const float*)d_in[8];
    float* out = (float*)d_out;

    const int nB = (NN + 255) / 256;
    const int eB = (NE + 255) / 256;

    // --- dtype detect + normalization + CSR build ---
    k_detect_zero<<<nB, 256>>>((const int*)ei);
    k_deg_count<<<eB, 256>>>(ei, ew);
    k_scan1<<<SCAN_NB, SCAN_B>>>();
    k_scan23<<<nB, 256>>>();
    k_fill<<<eB, 256>>>(ei, ew);

    const int gemm_blocks = (NN + 63) / 64;           // 782
    const int g128_blocks = (NN * 32 + 255) / 256;    // warp per node
    const int g64_blocks  = (NN * 16 + 255) / 256;    // half-warp per node

    // --- layer 1 (128 -> 128) ---
    k_gemm<128, true><<<gemm_blocks, 256>>>(x, W1);
    k_gather128<false><<<g128_blocks, 256>>>(b1, nullptr);

    // --- layer 2 (128 -> 128) ---
    k_gemm<128, false><<<gemm_blocks, 256>>>(nullptr, W2);
    k_gather128<false><<<g128_blocks, 256>>>(b2, nullptr);

    // --- layer 3 (128 -> 64) ---
    k_gemm<64, false><<<gemm_blocks, 256>>>(nullptr, W3);
    k_gather64<true><<<g64_blocks, 256>>>(b3, out);
}

// round 9
// speedup vs baseline: 1.3499x; 1.1432x over previous
#include <cuda_runtime.h>
#include <cuda_fp16.h>
#include <cstdint>

#define NN 50000
#define NE 800000
#define SCAN_B 512
#define SCAN_NB ((NN + SCAN_B - 1) / SCAN_B)  // 98

// ---------------------------------------------------------------------------
// Scratch (__device__ globals)
// ---------------------------------------------------------------------------
__device__ int    g_is64;
__device__ float  g_deg[NN];
__device__ float  g_dinv[NN];
__device__ int    g_cnt[NN];
__device__ int    g_off[NN + 1];
__device__ int    g_cursor[NN];
__device__ int    g_bsum[SCAN_NB];
__device__ int    g_src[NE];
__device__ float  g_coef[NE];
__device__ float4 g_h4[NN * 32];                 // activations [NN][128] fp32
__device__ __align__(16) __half2 g_mh[NN * 64];  // messages m [NN][D] fp16

// ---------------------------------------------------------------------------
// tf32 helpers
// ---------------------------------------------------------------------------
__device__ __forceinline__ uint32_t tf32_rna(float f) {
    uint32_t r;
    asm("cvt.rna.tf32.f32 %0, %1;" : "=r"(r) : "f"(f));
    return r;
}
// D += A(16x8 tf32) * B(8x8 tf32, col-major = W[n][k])
__device__ __forceinline__ void mma_tf32(float4& d, const uint32_t* a,
                                         uint32_t b0, uint32_t b1) {
    asm volatile(
        "mma.sync.aligned.m16n8k8.row.col.f32.tf32.tf32.f32 "
        "{%0,%1,%2,%3}, {%4,%5,%6,%7}, {%8,%9}, {%0,%1,%2,%3};"
        : "+f"(d.x), "+f"(d.y), "+f"(d.z), "+f"(d.w)
        : "r"(a[0]), "r"(a[1]), "r"(a[2]), "r"(a[3]), "r"(b0), "r"(b1));
}

// ---------------------------------------------------------------------------
// Fused: zero counters + dtype detect (int64 high words all zero) in block 0.
// ---------------------------------------------------------------------------
__global__ void k_detect_zero(const int* __restrict__ ei32) {
    int i = blockIdx.x * blockDim.x + threadIdx.x;
    if (i < NN) { g_deg[i] = 0.0f; g_cnt[i] = 0; }
    if (blockIdx.x == 0) {
        __shared__ int nz;
        if (threadIdx.x == 0) nz = 0;
        __syncthreads();
        for (int k = threadIdx.x; k < 2048; k += blockDim.x)
            if (ei32[2 * k + 1] != 0) nz = 1;
        __syncthreads();
        if (threadIdx.x == 0) g_is64 = (nz == 0) ? 1 : 0;
    }
}

__device__ __forceinline__ int load_idx(const void* ei, long i) {
    int v = g_is64 ? (int)((const long long*)ei)[i] : ((const int*)ei)[i];
    return min(max(v, 0), NN - 1);
}

// ---------------------------------------------------------------------------
// Normalization + CSR build
// ---------------------------------------------------------------------------
__global__ void k_deg_count(const void* __restrict__ ei, const float* __restrict__ ew) {
    int e = blockIdx.x * blockDim.x + threadIdx.x;
    if (e < NE) {
        int col = load_idx(ei, (long)NE + e);
        atomicAdd(&g_deg[col], ew[e]);
        atomicAdd(&g_cnt[col], 1);
    }
}

__global__ void k_scan1() {
    __shared__ int s[SCAN_B];
    int tid = threadIdx.x;
    int i = blockIdx.x * SCAN_B + tid;
    if (i < NN) g_dinv[i] = rsqrtf(g_deg[i] + 1.0f);  // self-loop weight 1
    int v = (i < NN) ? g_cnt[i] : 0;
    s[tid] = v;
    __syncthreads();
#pragma unroll
    for (int off = 1; off < SCAN_B; off <<= 1) {
        int t = (tid >= off) ? s[tid - off] : 0;
        __syncthreads();
        s[tid] += t;
        __syncthreads();
    }
    if (i < NN) g_off[i] = s[tid] - v;
    if (tid == SCAN_B - 1) g_bsum[blockIdx.x] = s[tid];
}

// fused scan2+scan3: every block re-scans the 98 block sums locally.
__global__ void k_scan23() {
    __shared__ int s[128];
    __shared__ int pre[SCAN_NB];
    int tid = threadIdx.x;
    int v = 0;
    if (tid < 128) { v = (tid < SCAN_NB) ? g_bsum[tid] : 0; s[tid] = v; }
    __syncthreads();
#pragma unroll
    for (int off = 1; off < 128; off <<= 1) {
        int t = 0;
        if (tid < 128 && tid >= off) t = s[tid - off];
        __syncthreads();
        if (tid < 128) s[tid] += t;
        __syncthreads();
    }
    if (tid < SCAN_NB) pre[tid] = s[tid] - v;
    __syncthreads();
    int i = blockIdx.x * blockDim.x + tid;
    if (i < NN) {
        int o = g_off[i] + pre[i / SCAN_B];
        g_off[i] = o;
        g_cursor[i] = o;
    }
    if (i == 0) g_off[NN] = NE;
}

__global__ void k_fill(const void* __restrict__ ei, const float* __restrict__ ew) {
    int e = blockIdx.x * blockDim.x + threadIdx.x;
    if (e < NE) {
        int row = load_idx(ei, e);
        int col = load_idx(ei, (long)NE + e);
        int pos = atomicAdd(&g_cursor[col], 1);
        pos = min(max(pos, 0), NE - 1);
        g_src[pos] = row;
        g_coef[pos] = g_dinv[row] * ew[e] * g_dinv[col];
    }
}

// ---------------------------------------------------------------------------
// Tensor-core GEMM via mma.sync tf32 (2-term split, 3 MMAs per subtile):
// m[i][j] = sum_k hin[i][k] * W[j][k],  W row-major [D][128].
// Block: 64 rows x D cols, 8 warps = 4 m-warps x 2 n-warps. K chunks of 32.
// Smem: W chunk as tf32 hi/lo uint32 [D][36-pad], h raw fp32 [64][36-pad].
// Fragment layouts per PTX ISA m16n8k8 (gid=lane>>2, tig=lane&3):
//   A: a0(gid,tig) a1(gid+8,tig) a2(gid,tig+4) a3(gid+8,tig+4)
//   B: b0(k=tig,n=gid) b1(k=tig+4,n=gid)   [B col-major = W[n][k] natural]
//   D: d0(gid,2tig) d1(gid,2tig+1) d2(gid+8,2tig) d3(gid+8,2tig+1)
// Epilogue: adjacent d-col pairs -> one half2 store each, no staging.
// ---------------------------------------------------------------------------
template <int D, bool FROM_X>
__global__ __launch_bounds__(256) void k_gemm_mma(const float* __restrict__ x,
                                                  const float* __restrict__ W) {
    const float* hin = FROM_X ? x : (const float*)g_h4;
    constexpr int NT = D / 16;  // n-tiles (8 cols) per n-warp (covers D/2 cols)
    __shared__ uint32_t Whi[D * 36];
    __shared__ uint32_t Wlo[D * 36];
    __shared__ alignas(16) float hs[64 * 36];

    const int tid = threadIdx.x;
    const int warp = tid >> 5, lane = tid & 31;
    const int wm = warp >> 1, wn = warp & 1;
    const int gid = lane >> 2, tig = lane & 3;
    const int row0 = blockIdx.x * 64;

    float4 acc[NT];
#pragma unroll
    for (int t = 0; t < NT; t++) acc[t] = make_float4(0.f, 0.f, 0.f, 0.f);

    for (int c = 0; c < 4; c++) {  // K chunks of 32
        // stage W chunk [D][32] -> tf32 hi/lo
        for (int idx = tid; idx < D * 32; idx += 256) {
            int n = idx >> 5, k = idx & 31;
            float wv = W[n * 128 + c * 32 + k];
            uint32_t h = tf32_rna(wv);
            uint32_t l = tf32_rna(wv - __uint_as_float(h));
            Whi[n * 36 + k] = h;
            Wlo[n * 36 + k] = l;
        }
        // stage h chunk [64][32] raw fp32
        for (int idx = tid; idx < 512; idx += 256) {
            int r = idx >> 3, kk4 = idx & 7;
            int gr = row0 + r;
            float4 v = (gr < NN) ? *(const float4*)(hin + (long)gr * 128 + c * 32 + kk4 * 4)
                                 : make_float4(0.f, 0.f, 0.f, 0.f);
            *(float4*)(hs + r * 36 + kk4 * 4) = v;
        }
        __syncthreads();

#pragma unroll
        for (int ks = 0; ks < 4; ks++) {  // K=8 steps
            const int k0 = ks * 8;
            float a0 = hs[(wm * 16 + gid) * 36 + k0 + tig];
            float a1 = hs[(wm * 16 + gid + 8) * 36 + k0 + tig];
            float a2 = hs[(wm * 16 + gid) * 36 + k0 + tig + 4];
            float a3 = hs[(wm * 16 + gid + 8) * 36 + k0 + tig + 4];
            uint32_t ahi[4], alo[4];
            float ar[4] = {a0, a1, a2, a3};
#pragma unroll
            for (int q = 0; q < 4; q++) {
                ahi[q] = tf32_rna(ar[q]);
                alo[q] = tf32_rna(ar[q] - __uint_as_float(ahi[q]));
            }
#pragma unroll
            for (int t = 0; t < NT; t++) {
                int n = wn * (D / 2) + t * 8 + gid;
                uint32_t bh0 = Whi[n * 36 + k0 + tig];
                uint32_t bh1 = Whi[n * 36 + k0 + tig + 4];
                uint32_t bl0 = Wlo[n * 36 + k0 + tig];
                uint32_t bl1 = Wlo[n * 36 + k0 + tig + 4];
                mma_tf32(acc[t], ahi, bh0, bh1);
                mma_tf32(acc[t], alo, bh0, bh1);
                mma_tf32(acc[t], ahi, bl0, bl1);
            }
        }
        __syncthreads();
    }

    // epilogue: pack adjacent cols -> half2, direct store
    const int r0 = row0 + wm * 16 + gid;
    const int r1 = r0 + 8;
#pragma unroll
    for (int t = 0; t < NT; t++) {
        int cidx = wn * (D / 4) + t * 4 + tig;  // half2 index within row
        if (r0 < NN) g_mh[(long)r0 * (D / 2) + cidx] = __floats2half2_rn(acc[t].x, acc[t].y);
        if (r1 < NN) g_mh[(long)r1 * (D / 2) + cidx] = __floats2half2_rn(acc[t].z, acc[t].w);
    }
}

// ---------------------------------------------------------------------------
// Gather-reduce per destination node, fused self-loop + bias + ReLU.
// m rows fp16, fp32 accumulate. No atomics.
// ---------------------------------------------------------------------------
template <bool TO_OUT>
__global__ __launch_bounds__(256) void k_gather128(const float* __restrict__ b,
                                                   float* __restrict__ outp) {
    int n = (blockIdx.x * blockDim.x + threadIdx.x) >> 5;
    int lane = threadIdx.x & 31;
    if (n >= NN) return;
    const uint2* mh = (const uint2*)g_mh;  // row = 32 uint2
    int beg = g_off[n], end = g_off[n + 1];
    float dn = g_dinv[n];
    float sl = dn * dn;
    float4 acc;
    {
        uint2 raw = mh[(long)n * 32 + lane];
        float2 a0 = __half22float2(*(const __half2*)&raw.x);
        float2 a1 = __half22float2(*(const __half2*)&raw.y);
        acc = make_float4(a0.x * sl, a0.y * sl, a1.x * sl, a1.y * sl);
    }
#pragma unroll 4
    for (int i = beg; i < end; i++) {
        int s = g_src[i];
        float cf = g_coef[i];
        uint2 raw = mh[(long)s * 32 + lane];
        float2 v0 = __half22float2(*(const __half2*)&raw.x);
        float2 v1 = __half22float2(*(const __half2*)&raw.y);
        acc.x += cf * v0.x; acc.y += cf * v0.y;
        acc.z += cf * v1.x; acc.w += cf * v1.y;
    }
    int j = lane * 4;
    acc.x = fmaxf(acc.x + __ldg(b + j + 0), 0.0f);
    acc.y = fmaxf(acc.y + __ldg(b + j + 1), 0.0f);
    acc.z = fmaxf(acc.z + __ldg(b + j + 2), 0.0f);
    acc.w = fmaxf(acc.w + __ldg(b + j + 3), 0.0f);
    if (TO_OUT) ((float4*)outp)[n * 32 + lane] = acc;
    else        g_h4[n * 32 + lane] = acc;
}

template <bool TO_OUT>
__global__ __launch_bounds__(256) void k_gather64(const float* __restrict__ b,
                                                  float* __restrict__ outp) {
    int gw = (blockIdx.x * blockDim.x + threadIdx.x) >> 5;
    int lane = threadIdx.x & 31;
    int n = gw * 2 + (lane >> 4);
    int l = lane & 15;
    if (n >= NN) return;
    const uint2* mh = (const uint2*)g_mh;  // row = 16 uint2
    int beg = g_off[n], end = g_off[n + 1];
    float dn = g_dinv[n];
    float sl = dn * dn;
    float4 acc;
    {
        uint2 raw = mh[(long)n * 16 + l];
        float2 a0 = __half22float2(*(const __half2*)&raw.x);
        float2 a1 = __half22float2(*(const __half2*)&raw.y);
        acc = make_float4(a0.x * sl, a0.y * sl, a1.x * sl, a1.y * sl);
    }
#pragma unroll 4
    for (int i = beg; i < end; i++) {
        int s = g_src[i];
        float cf = g_coef[i];
        uint2 raw = mh[(long)s * 16 + l];
        float2 v0 = __half22float2(*(const __half2*)&raw.x);
        float2 v1 = __half22float2(*(const __half2*)&raw.y);
        acc.x += cf * v0.x; acc.y += cf * v0.y;
        acc.z += cf * v1.x; acc.w += cf * v1.y;
    }
    int j = l * 4;
    acc.x = fmaxf(acc.x + __ldg(b + j + 0), 0.0f);
    acc.y = fmaxf(acc.y + __ldg(b + j + 1), 0.0f);
    acc.z = fmaxf(acc.z + __ldg(b + j + 2), 0.0f);
    acc.w = fmaxf(acc.w + __ldg(b + j + 3), 0.0f);
    if (TO_OUT) ((float4*)outp)[n * 16 + l] = acc;
    else        g_h4[n * 16 + l] = acc;
}

// ---------------------------------------------------------------------------
extern "C" void kernel_launch(void* const* d_in, const int* in_sizes, int n_in,
                              void* d_out, int out_size) {
    const float* x = (const float*)d_in[0];
    const void*  ei = d_in[1];
    const float* ew = (const float*)d_in[2];
    const float* W1 = (const float*)d_in[3];
    const float* b1 = (const float*)d_in[4];
    const float* W2 = (const float*)d_in[5];
    const float* b2 = (const float*)d_in[6];
    const float* W3 = (const float*)d_in[7];
    const float* b3 = (const float*)d_in[8];
    float* out = (float*)d_out;

    const int nB = (NN + 255) / 256;
    const int eB = (NE + 255) / 256;

    // --- dtype detect + normalization + CSR build ---
    k_detect_zero<<<nB, 256>>>((const int*)ei);
    k_deg_count<<<eB, 256>>>(ei, ew);
    k_scan1<<<SCAN_NB, SCAN_B>>>();
    k_scan23<<<nB, 256>>>();
    k_fill<<<eB, 256>>>(ei, ew);

    const int gemm_blocks = (NN + 63) / 64;           // 782
    const int g128_blocks = (NN * 32 + 255) / 256;
    const int g64_blocks  = (NN * 16 + 255) / 256;

    // --- layer 1 (128 -> 128) ---
    k_gemm_mma<128, true><<<gemm_blocks, 256>>>(x, W1);
    k_gather128<false><<<g128_blocks, 256>>>(b1, nullptr);

    // --- layer 2 (128 -> 128) ---
    k_gemm_mma<128, false><<<gemm_blocks, 256>>>(nullptr, W2);
    k_gather128<false><<<g128_blocks, 256>>>(b2, nullptr);

    // --- layer 3 (128 -> 64) ---
    k_gemm_mma<64, false><<<gemm_blocks, 256>>>(nullptr, W3);
    k_gather64<true><<<g64_blocks, 256>>>(b3, out);
}

// round 10
// speedup vs baseline: 1.6797x; 1.2443x over previous
#include <cuda_runtime.h>
#include <cuda_fp16.h>
#include <cstdint>

#define NN 50000
#define NE 800000
#define SCAN_B 512
#define SCAN_NB ((NN + SCAN_B - 1) / SCAN_B)  // 98

// ---------------------------------------------------------------------------
// Scratch (__device__ globals)
// ---------------------------------------------------------------------------
__device__ int                g_is64;
__device__ unsigned long long g_degcnt[NN];  // cnt in bits[40..], weight*2^32 in bits[0..40)
__device__ float              g_dinv[NN];
__device__ int                g_off[NN + 1];
__device__ int                g_cursor[NN];
__device__ int                g_bsum[SCAN_NB];
__device__ int                g_src[NE];
__device__ float              g_coef[NE];
__device__ float4             g_h4[NN * 32];                 // activations [NN][128] fp32
__device__ __align__(16) __half2 g_mh[NN * 64];              // messages m [NN][D] fp16

// ---------------------------------------------------------------------------
// tf32 helpers
// ---------------------------------------------------------------------------
__device__ __forceinline__ uint32_t tf32_rna(float f) {
    uint32_t r;
    asm("cvt.rna.tf32.f32 %0, %1;" : "=r"(r) : "f"(f));
    return r;
}
__device__ __forceinline__ void mma_tf32(float4& d, const uint32_t* a,
                                         uint32_t b0, uint32_t b1) {
    asm volatile(
        "mma.sync.aligned.m16n8k8.row.col.f32.tf32.tf32.f32 "
        "{%0,%1,%2,%3}, {%4,%5,%6,%7}, {%8,%9}, {%0,%1,%2,%3};"
        : "+f"(d.x), "+f"(d.y), "+f"(d.z), "+f"(d.w)
        : "r"(a[0]), "r"(a[1]), "r"(a[2]), "r"(a[3]), "r"(b0), "r"(b1));
}

// ---------------------------------------------------------------------------
// Fused: zero counters + dtype detect (int64 high words all zero) in block 0.
// ---------------------------------------------------------------------------
__global__ void k_detect_zero(const int* __restrict__ ei32) {
    int i = blockIdx.x * blockDim.x + threadIdx.x;
    if (i < NN) g_degcnt[i] = 0ull;
    if (blockIdx.x == 0) {
        __shared__ int nz;
        if (threadIdx.x == 0) nz = 0;
        __syncthreads();
        for (int k = threadIdx.x; k < 2048; k += blockDim.x)
            if (ei32[2 * k + 1] != 0) nz = 1;
        __syncthreads();
        if (threadIdx.x == 0) g_is64 = (nz == 0) ? 1 : 0;
    }
}

__device__ __forceinline__ int load_idx(const void* ei, long i) {
    int v = g_is64 ? (int)((const long long*)ei)[i] : ((const int*)ei)[i];
    return min(max(v, 0), NN - 1);
}

// ---------------------------------------------------------------------------
// Normalization + CSR build. One packed 64-bit atomic per edge:
// +(1<<40) counts the edge, low 40 bits accumulate weight in 2^-32 fixed pt.
// (w in [0,1); max ~2^8 edges/node -> weight sum < 2^40, cnt < 2^24.)
// ---------------------------------------------------------------------------
__global__ void k_deg_count(const void* __restrict__ ei, const float* __restrict__ ew) {
    int e = blockIdx.x * blockDim.x + threadIdx.x;
    if (e < NE) {
        int col = load_idx(ei, (long)NE + e);
        float w = ew[e];
        unsigned long long v =
            (1ull << 40) | (unsigned long long)(w * 4294967296.0f);
        atomicAdd(&g_degcnt[col], v);
    }
}

// scan step 1, fused with dinv decode (degcnt final here)
__global__ void k_scan1() {
    __shared__ int s[SCAN_B];
    int tid = threadIdx.x;
    int i = blockIdx.x * SCAN_B + tid;
    int v = 0;
    if (i < NN) {
        unsigned long long dc = g_degcnt[i];
        float deg = (float)(dc & 0xFFFFFFFFFFull) * 2.3283064365386963e-10f;
        g_dinv[i] = rsqrtf(deg + 1.0f);  // self-loop weight 1
        v = (int)(dc >> 40);
    }
    s[tid] = v;
    __syncthreads();
#pragma unroll
    for (int off = 1; off < SCAN_B; off <<= 1) {
        int t = (tid >= off) ? s[tid - off] : 0;
        __syncthreads();
        s[tid] += t;
        __syncthreads();
    }
    if (i < NN) g_off[i] = s[tid] - v;
    if (tid == SCAN_B - 1) g_bsum[blockIdx.x] = s[tid];
}

// fused scan2+scan3: every block re-scans the 98 block sums locally.
__global__ void k_scan23() {
    __shared__ int s[128];
    __shared__ int pre[SCAN_NB];
    int tid = threadIdx.x;
    int v = 0;
    if (tid < 128) { v = (tid < SCAN_NB) ? g_bsum[tid] : 0; s[tid] = v; }
    __syncthreads();
#pragma unroll
    for (int off = 1; off < 128; off <<= 1) {
        int t = 0;
        if (tid < 128 && tid >= off) t = s[tid - off];
        __syncthreads();
        if (tid < 128) s[tid] += t;
        __syncthreads();
    }
    if (tid < SCAN_NB) pre[tid] = s[tid] - v;
    __syncthreads();
    int i = blockIdx.x * blockDim.x + tid;
    if (i < NN) {
        int o = g_off[i] + pre[i / SCAN_B];
        g_off[i] = o;
        g_cursor[i] = o;
    }
    if (i == 0) g_off[NN] = NE;
}

__global__ void k_fill(const void* __restrict__ ei, const float* __restrict__ ew) {
    int e = blockIdx.x * blockDim.x + threadIdx.x;
    if (e < NE) {
        int row = load_idx(ei, e);
        int col = load_idx(ei, (long)NE + e);
        int pos = atomicAdd(&g_cursor[col], 1);
        pos = min(max(pos, 0), NE - 1);
        g_src[pos] = row;
        g_coef[pos] = g_dinv[row] * ew[e] * g_dinv[col];
    }
}

// ---------------------------------------------------------------------------
// Tensor-core GEMM, single tf32 MMA per subtile (error attenuated by the
// downstream ~17-edge aggregation, same mechanism measured for fp16 m).
// Block: 64 rows x D cols, 8 warps = 2 m-warps x 4 n-warps; each warp owns
// two m16 subtiles sharing B-fragments (33% fewer LDS per MMA than R9).
// ---------------------------------------------------------------------------
template <int D, bool FROM_X>
__global__ __launch_bounds__(256) void k_gemm_mma(const float* __restrict__ x,
                                                  const float* __restrict__ W) {
    const float* hin = FROM_X ? x : (const float*)g_h4;
    constexpr int NT = D / 32;  // 8-col tiles per n-warp (n-warp covers D/4 cols)
    __shared__ uint32_t Whi[D * 36];
    __shared__ alignas(16) float hs[64 * 36];

    const int tid = threadIdx.x;
    const int warp = tid >> 5, lane = tid & 31;
    const int wm = warp >> 2, wn = warp & 3;  // 2 m-warps x 4 n-warps
    const int gid = lane >> 2, tig = lane & 3;
    const int row0 = blockIdx.x * 64;

    float4 acc[2][NT];
#pragma unroll
    for (int s = 0; s < 2; s++)
#pragma unroll
        for (int t = 0; t < NT; t++) acc[s][t] = make_float4(0.f, 0.f, 0.f, 0.f);

    for (int c = 0; c < 4; c++) {  // K chunks of 32
        for (int idx = tid; idx < D * 32; idx += 256) {
            int n = idx >> 5, k = idx & 31;
            Whi[n * 36 + k] = tf32_rna(W[n * 128 + c * 32 + k]);
        }
        for (int idx = tid; idx < 512; idx += 256) {
            int r = idx >> 3, kk4 = idx & 7;
            int gr = row0 + r;
            float4 v = (gr < NN) ? *(const float4*)(hin + (long)gr * 128 + c * 32 + kk4 * 4)
                                 : make_float4(0.f, 0.f, 0.f, 0.f);
            *(float4*)(hs + r * 36 + kk4 * 4) = v;
        }
        __syncthreads();

#pragma unroll
        for (int ks = 0; ks < 4; ks++) {  // K=8 steps
            const int k0 = ks * 8;
            uint32_t a[2][4];
#pragma unroll
            for (int s = 0; s < 2; s++) {
                const int rb = wm * 32 + s * 16;
                a[s][0] = tf32_rna(hs[(rb + gid) * 36 + k0 + tig]);
                a[s][1] = tf32_rna(hs[(rb + gid + 8) * 36 + k0 + tig]);
                a[s][2] = tf32_rna(hs[(rb + gid) * 36 + k0 + tig + 4]);
                a[s][3] = tf32_rna(hs[(rb + gid + 8) * 36 + k0 + tig + 4]);
            }
#pragma unroll
            for (int t = 0; t < NT; t++) {
                int n = wn * (D / 4) + t * 8 + gid;
                uint32_t b0 = Whi[n * 36 + k0 + tig];
                uint32_t b1 = Whi[n * 36 + k0 + tig + 4];
                mma_tf32(acc[0][t], a[0], b0, b1);
                mma_tf32(acc[1][t], a[1], b0, b1);
            }
        }
        __syncthreads();
    }

    // epilogue: adjacent d-col pairs -> half2, direct store
#pragma unroll
    for (int s = 0; s < 2; s++) {
        const int r0 = row0 + wm * 32 + s * 16 + gid;
        const int r1 = r0 + 8;
#pragma unroll
        for (int t = 0; t < NT; t++) {
            int cidx = wn * (D / 8) + t * 4 + tig;  // half2 index within row
            if (r0 < NN) g_mh[(long)r0 * (D / 2) + cidx] = __floats2half2_rn(acc[s][t].x, acc[s][t].y);
            if (r1 < NN) g_mh[(long)r1 * (D / 2) + cidx] = __floats2half2_rn(acc[s][t].z, acc[s][t].w);
        }
    }
}

// ---------------------------------------------------------------------------
// Gather-reduce per destination node, fused self-loop + bias + ReLU.
// m rows fp16, fp32 accumulate. No atomics.
// ---------------------------------------------------------------------------
template <bool TO_OUT>
__global__ __launch_bounds__(256) void k_gather128(const float* __restrict__ b,
                                                   float* __restrict__ outp) {
    int n = (blockIdx.x * blockDim.x + threadIdx.x) >> 5;
    int lane = threadIdx.x & 31;
    if (n >= NN) return;
    const uint2* mh = (const uint2*)g_mh;  // row = 32 uint2
    int beg = g_off[n], end = g_off[n + 1];
    float dn = g_dinv[n];
    float sl = dn * dn;
    float4 acc;
    {
        uint2 raw = mh[(long)n * 32 + lane];
        float2 a0 = __half22float2(*(const __half2*)&raw.x);
        float2 a1 = __half22float2(*(const __half2*)&raw.y);
        acc = make_float4(a0.x * sl, a0.y * sl, a1.x * sl, a1.y * sl);
    }
#pragma unroll 4
    for (int i = beg; i < end; i++) {
        int s = g_src[i];
        float cf = g_coef[i];
        uint2 raw = mh[(long)s * 32 + lane];
        float2 v0 = __half22float2(*(const __half2*)&raw.x);
        float2 v1 = __half22float2(*(const __half2*)&raw.y);
        acc.x += cf * v0.x; acc.y += cf * v0.y;
        acc.z += cf * v1.x; acc.w += cf * v1.y;
    }
    int j = lane * 4;
    acc.x = fmaxf(acc.x + __ldg(b + j + 0), 0.0f);
    acc.y = fmaxf(acc.y + __ldg(b + j + 1), 0.0f);
    acc.z = fmaxf(acc.z + __ldg(b + j + 2), 0.0f);
    acc.w = fmaxf(acc.w + __ldg(b + j + 3), 0.0f);
    if (TO_OUT) ((float4*)outp)[n * 32 + lane] = acc;
    else        g_h4[n * 32 + lane] = acc;
}

template <bool TO_OUT>
__global__ __launch_bounds__(256) void k_gather64(const float* __restrict__ b,
                                                  float* __restrict__ outp) {
    int gw = (blockIdx.x * blockDim.x + threadIdx.x) >> 5;
    int lane = threadIdx.x & 31;
    int n = gw * 2 + (lane >> 4);
    int l = lane & 15;
    if (n >= NN) return;
    const uint2* mh = (const uint2*)g_mh;  // row = 16 uint2
    int beg = g_off[n], end = g_off[n + 1];
    float dn = g_dinv[n];
    float sl = dn * dn;
    float4 acc;
    {
        uint2 raw = mh[(long)n * 16 + l];
        float2 a0 = __half22float2(*(const __half2*)&raw.x);
        float2 a1 = __half22float2(*(const __half2*)&raw.y);
        acc = make_float4(a0.x * sl, a0.y * sl, a1.x * sl, a1.y * sl);
    }
#pragma unroll 4
    for (int i = beg; i < end; i++) {
        int s = g_src[i];
        float cf = g_coef[i];
        uint2 raw = mh[(long)s * 16 + l];
        float2 v0 = __half22float2(*(const __half2*)&raw.x);
        float2 v1 = __half22float2(*(const __half2*)&raw.y);
        acc.x += cf * v0.x; acc.y += cf * v0.y;
        acc.z += cf * v1.x; acc.w += cf * v1.y;
    }
    int j = l * 4;
    acc.x = fmaxf(acc.x + __ldg(b + j + 0), 0.0f);
    acc.y = fmaxf(acc.y + __ldg(b + j + 1), 0.0f);
    acc.z = fmaxf(acc.z + __ldg(b + j + 2), 0.0f);
    acc.w = fmaxf(acc.w + __ldg(b + j + 3), 0.0f);
    if (TO_OUT) ((float4*)outp)[n * 16 + l] = acc;
    else        g_h4[n * 16 + l] = acc;
}

// ---------------------------------------------------------------------------
extern "C" void kernel_launch(void* const* d_in, const int* in_sizes, int n_in,
                              void* d_out, int out_size) {
    const float* x = (const float*)d_in[0];
    const void*  ei = d_in[1];
    const float* ew = (const float*)d_in[2];
    const float* W1 = (const float*)d_in[3];
    const float* b1 = (const float*)d_in[4];
    const float* W2 = (const float*)d_in[5];
    const float* b2 = (const float*)d_in[6];
    const float* W3 = (const float*)d_in[7];
    const float* b3 = (const float*)d_in[8];
    float* out = (float*)d_out;

    const int nB = (NN + 255) / 256;
    const int eB = (NE + 255) / 256;

    // --- dtype detect + normalization + CSR build ---
    k_detect_zero<<<nB, 256>>>((const int*)ei);
    k_deg_count<<<eB, 256>>>(ei, ew);
    k_scan1<<<SCAN_NB, SCAN_B>>>();
    k_scan23<<<nB, 256>>>();
    k_fill<<<eB, 256>>>(ei, ew);

    const int gemm_blocks = (NN + 63) / 64;           // 782
    const int g128_blocks = (NN * 32 + 255) / 256;
    const int g64_blocks  = (NN * 16 + 255) / 256;

    // --- layer 1 (128 -> 128) ---
    k_gemm_mma<128, true><<<gemm_blocks, 256>>>(x, W1);
    k_gather128<false><<<g128_blocks, 256>>>(b1, nullptr);

    // --- layer 2 (128 -> 128) ---
    k_gemm_mma<128, false><<<gemm_blocks, 256>>>(nullptr, W2);
    k_gather128<false><<<g128_blocks, 256>>>(b2, nullptr);

    // --- layer 3 (128 -> 64) ---
    k_gemm_mma<64, false><<<gemm_blocks, 256>>>(nullptr, W3);
    k_gather64<true><<<g64_blocks, 256>>>(b3, out);
}

// round 11
// speedup vs baseline: 1.9517x; 1.1619x over previous
#include <cuda_runtime.h>
#include <cuda_fp16.h>
#include <cstdint>

#define NN 50000
#define NE 800000
#define SCAN_B 512
#define SCAN_NB ((NN + SCAN_B - 1) / SCAN_B)  // 98

// ---------------------------------------------------------------------------
// Scratch (__device__ globals)
// ---------------------------------------------------------------------------
__device__ int                g_is64;
__device__ unsigned long long g_degcnt[NN];  // cnt in bits[40..], weight*2^-32 fixed pt low
__device__ float              g_dinv[NN];
__device__ int                g_off[NN + 1];
__device__ int                g_cursor[NN];
__device__ int                g_bsum[SCAN_NB];
__device__ int                g_src[NE];
__device__ float              g_coef[NE];
__device__ __align__(16) __half2 g_hh[NN * 64];  // activations h [NN][128] fp16
__device__ __align__(16) __half2 g_mh[NN * 64];  // messages m [NN][D] fp16

// ---------------------------------------------------------------------------
// fp16 MMA m16n8k16, fp32 accumulate
// ---------------------------------------------------------------------------
__device__ __forceinline__ void mma_f16(float4& d, uint32_t a0, uint32_t a1,
                                        uint32_t a2, uint32_t a3,
                                        uint32_t b0, uint32_t b1) {
    asm volatile(
        "mma.sync.aligned.m16n8k16.row.col.f32.f16.f16.f32 "
        "{%0,%1,%2,%3}, {%4,%5,%6,%7}, {%8,%9}, {%0,%1,%2,%3};"
        : "+f"(d.x), "+f"(d.y), "+f"(d.z), "+f"(d.w)
        : "r"(a0), "r"(a1), "r"(a2), "r"(a3), "r"(b0), "r"(b1));
}

// ---------------------------------------------------------------------------
// Fused: zero counters + dtype detect (int64 high words all zero) in block 0.
// ---------------------------------------------------------------------------
__global__ void k_detect_zero(const int* __restrict__ ei32) {
    int i = blockIdx.x * blockDim.x + threadIdx.x;
    if (i < NN) g_degcnt[i] = 0ull;
    if (blockIdx.x == 0) {
        __shared__ int nz;
        if (threadIdx.x == 0) nz = 0;
        __syncthreads();
        for (int k = threadIdx.x; k < 2048; k += blockDim.x)
            if (ei32[2 * k + 1] != 0) nz = 1;
        __syncthreads();
        if (threadIdx.x == 0) g_is64 = (nz == 0) ? 1 : 0;
    }
}

__device__ __forceinline__ int load_idx(const void* ei, long i) {
    int v = g_is64 ? (int)((const long long*)ei)[i] : ((const int*)ei)[i];
    return min(max(v, 0), NN - 1);
}

// ---------------------------------------------------------------------------
// Normalization + CSR build (packed 64-bit deg+cnt atomic, proven R10)
// ---------------------------------------------------------------------------
__global__ void k_deg_count(const void* __restrict__ ei, const float* __restrict__ ew) {
    int e = blockIdx.x * blockDim.x + threadIdx.x;
    if (e < NE) {
        int col = load_idx(ei, (long)NE + e);
        float w = ew[e];
        unsigned long long v =
            (1ull << 40) | (unsigned long long)(w * 4294967296.0f);
        atomicAdd(&g_degcnt[col], v);
    }
}

__global__ void k_scan1() {
    __shared__ int s[SCAN_B];
    int tid = threadIdx.x;
    int i = blockIdx.x * SCAN_B + tid;
    int v = 0;
    if (i < NN) {
        unsigned long long dc = g_degcnt[i];
        float deg = (float)(dc & 0xFFFFFFFFFFull) * 2.3283064365386963e-10f;
        g_dinv[i] = rsqrtf(deg + 1.0f);  // self-loop weight 1
        v = (int)(dc >> 40);
    }
    s[tid] = v;
    __syncthreads();
#pragma unroll
    for (int off = 1; off < SCAN_B; off <<= 1) {
        int t = (tid >= off) ? s[tid - off] : 0;
        __syncthreads();
        s[tid] += t;
        __syncthreads();
    }
    if (i < NN) g_off[i] = s[tid] - v;
    if (tid == SCAN_B - 1) g_bsum[blockIdx.x] = s[tid];
}

__global__ void k_scan23() {
    __shared__ int s[128];
    __shared__ int pre[SCAN_NB];
    int tid = threadIdx.x;
    int v = 0;
    if (tid < 128) { v = (tid < SCAN_NB) ? g_bsum[tid] : 0; s[tid] = v; }
    __syncthreads();
#pragma unroll
    for (int off = 1; off < 128; off <<= 1) {
        int t = 0;
        if (tid < 128 && tid >= off) t = s[tid - off];
        __syncthreads();
        if (tid < 128) s[tid] += t;
        __syncthreads();
    }
    if (tid < SCAN_NB) pre[tid] = s[tid] - v;
    __syncthreads();
    int i = blockIdx.x * blockDim.x + tid;
    if (i < NN) {
        int o = g_off[i] + pre[i / SCAN_B];
        g_off[i] = o;
        g_cursor[i] = o;
    }
    if (i == 0) g_off[NN] = NE;
}

__global__ void k_fill(const void* __restrict__ ei, const float* __restrict__ ew) {
    int e = blockIdx.x * blockDim.x + threadIdx.x;
    if (e < NE) {
        int row = load_idx(ei, e);
        int col = load_idx(ei, (long)NE + e);
        int pos = atomicAdd(&g_cursor[col], 1);
        pos = min(max(pos, 0), NE - 1);
        g_src[pos] = row;
        g_coef[pos] = g_dinv[row] * ew[e] * g_dinv[col];
    }
}

// ---------------------------------------------------------------------------
// fp16 tensor-core GEMM: m[i][j] = sum_k h[i][k] * W[j][k], fp32 accumulate.
// Block: 64 rows x D cols, 8 warps = 2 m-warps x 4 n-warps, each warp two
// m16 subtiles sharing B. K chunks of 32 = 2 x k16 MMA steps; no converts
// in the inner loop (h stored fp16; W pre-converted during staging).
// Smem rows padded to 20 half2: gid*20+tig covers all 32 banks (verified).
// m16n8k16 fragments (gid=lane>>2, tig=lane&3):
//   A: a0(gid, 2tig:+1) a1(gid+8, 2tig:+1) a2(gid, 2tig+8:+9) a3(gid+8, ...)
//   B col-major: b0(k=2tig:+1, n=gid) b1(k=2tig+8:+9, n=gid)
//   D: d0(gid,2tig) d1(gid,2tig+1) d2(gid+8,2tig) d3(gid+8,2tig+1)
// ---------------------------------------------------------------------------
template <int D, bool FROM_X>
__global__ __launch_bounds__(256) void k_gemm_h(const float* __restrict__ x,
                                                const float* __restrict__ W) {
    constexpr int NT = D / 32;  // 8-col tiles per n-warp
    __shared__ __half2 Wh[D * 20];
    __shared__ __half2 hs2[64 * 20];

    const int tid = threadIdx.x;
    const int warp = tid >> 5, lane = tid & 31;
    const int wm = warp >> 2, wn = warp & 3;  // 2 m-warps x 4 n-warps
    const int gid = lane >> 2, tig = lane & 3;
    const int row0 = blockIdx.x * 64;

    float4 acc[2][NT];
#pragma unroll
    for (int s = 0; s < 2; s++)
#pragma unroll
        for (int t = 0; t < NT; t++) acc[s][t] = make_float4(0.f, 0.f, 0.f, 0.f);

    for (int c = 0; c < 4; c++) {  // K chunks of 32
        // stage W chunk [D][32] -> half2 (16 per row, pad 20)
        for (int idx = tid; idx < D * 16; idx += 256) {
            int n = idx >> 4, kk = idx & 15;
            float2 wv = *(const float2*)(W + n * 128 + c * 32 + kk * 2);
            Wh[n * 20 + kk] = __floats2half2_rn(wv.x, wv.y);
        }
        // stage h chunk [64][32] as half2
        for (int idx = tid; idx < 512; idx += 256) {
            int r = idx >> 3, q = idx & 7;  // q = pair of half2 (4 cols)
            int gr = row0 + r;
            uint2 packed;
            if (gr < NN) {
                if (FROM_X) {
                    float4 v = *(const float4*)(x + (long)gr * 128 + c * 32 + q * 4);
                    __half2 p0 = __floats2half2_rn(v.x, v.y);
                    __half2 p1 = __floats2half2_rn(v.z, v.w);
                    packed.x = *(const uint32_t*)&p0;
                    packed.y = *(const uint32_t*)&p1;
                } else {
                    packed = *(const uint2*)(g_hh + (long)gr * 64 + c * 16 + q * 2);
                }
            } else {
                packed.x = 0u; packed.y = 0u;
            }
            *(uint2*)(hs2 + r * 20 + q * 2) = packed;
        }
        __syncthreads();

        const uint32_t* whu = (const uint32_t*)Wh;
        const uint32_t* hsu = (const uint32_t*)hs2;
#pragma unroll
        for (int ks = 0; ks < 2; ks++) {  // k16 steps
            const int kb = ks * 8;
            uint32_t a[2][4];
#pragma unroll
            for (int s = 0; s < 2; s++) {
                const int rb = wm * 32 + s * 16;
                a[s][0] = hsu[(rb + gid) * 20 + kb + tig];
                a[s][1] = hsu[(rb + gid + 8) * 20 + kb + tig];
                a[s][2] = hsu[(rb + gid) * 20 + kb + tig + 4];
                a[s][3] = hsu[(rb + gid + 8) * 20 + kb + tig + 4];
            }
#pragma unroll
            for (int t = 0; t < NT; t++) {
                int n = wn * (D / 4) + t * 8 + gid;
                uint32_t b0 = whu[n * 20 + kb + tig];
                uint32_t b1 = whu[n * 20 + kb + tig + 4];
                mma_f16(acc[0][t], a[0][0], a[0][1], a[0][2], a[0][3], b0, b1);
                mma_f16(acc[1][t], a[1][0], a[1][1], a[1][2], a[1][3], b0, b1);
            }
        }
        __syncthreads();
    }

    // epilogue: adjacent d-col pairs -> half2, direct store
#pragma unroll
    for (int s = 0; s < 2; s++) {
        const int r0 = row0 + wm * 32 + s * 16 + gid;
        const int r1 = r0 + 8;
#pragma unroll
        for (int t = 0; t < NT; t++) {
            int cidx = wn * (D / 8) + t * 4 + tig;  // half2 index within row
            if (r0 < NN) g_mh[(long)r0 * (D / 2) + cidx] = __floats2half2_rn(acc[s][t].x, acc[s][t].y);
            if (r1 < NN) g_mh[(long)r1 * (D / 2) + cidx] = __floats2half2_rn(acc[s][t].z, acc[s][t].w);
        }
    }
}

// ---------------------------------------------------------------------------
// Gather-reduce per destination node, fused self-loop + bias + ReLU.
// m fp16, fp32 accumulate; h output written fp16 (half the store traffic).
// ---------------------------------------------------------------------------
template <bool TO_OUT>
__global__ __launch_bounds__(256) void k_gather128(const float* __restrict__ b,
                                                   float* __restrict__ outp) {
    int n = (blockIdx.x * blockDim.x + threadIdx.x) >> 5;
    int lane = threadIdx.x & 31;
    if (n >= NN) return;
    const uint2* mh = (const uint2*)g_mh;  // row = 32 uint2
    int beg = g_off[n], end = g_off[n + 1];
    float dn = g_dinv[n];
    float sl = dn * dn;
    float4 acc;
    {
        uint2 raw = mh[(long)n * 32 + lane];
        float2 a0 = __half22float2(*(const __half2*)&raw.x);
        float2 a1 = __half22float2(*(const __half2*)&raw.y);
        acc = make_float4(a0.x * sl, a0.y * sl, a1.x * sl, a1.y * sl);
    }
#pragma unroll 4
    for (int i = beg; i < end; i++) {
        int s = g_src[i];
        float cf = g_coef[i];
        uint2 raw = mh[(long)s * 32 + lane];
        float2 v0 = __half22float2(*(const __half2*)&raw.x);
        float2 v1 = __half22float2(*(const __half2*)&raw.y);
        acc.x += cf * v0.x; acc.y += cf * v0.y;
        acc.z += cf * v1.x; acc.w += cf * v1.y;
    }
    int j = lane * 4;
    acc.x = fmaxf(acc.x + __ldg(b + j + 0), 0.0f);
    acc.y = fmaxf(acc.y + __ldg(b + j + 1), 0.0f);
    acc.z = fmaxf(acc.z + __ldg(b + j + 2), 0.0f);
    acc.w = fmaxf(acc.w + __ldg(b + j + 3), 0.0f);
    if (TO_OUT) {
        ((float4*)outp)[n * 32 + lane] = acc;
    } else {
        __half2 p0 = __floats2half2_rn(acc.x, acc.y);
        __half2 p1 = __floats2half2_rn(acc.z, acc.w);
        uint2 packed;
        packed.x = *(const uint32_t*)&p0;
        packed.y = *(const uint32_t*)&p1;
        *(uint2*)(g_hh + (long)n * 64 + lane * 2) = packed;
    }
}

// D=64 final layer: half-warp per node, fp32 out
__global__ __launch_bounds__(256) void k_gather64_out(const float* __restrict__ b,
                                                      float* __restrict__ outp) {
    int gw = (blockIdx.x * blockDim.x + threadIdx.x) >> 5;
    int lane = threadIdx.x & 31;
    int n = gw * 2 + (lane >> 4);
    int l = lane & 15;
    if (n >= NN) return;
    const uint2* mh = (const uint2*)g_mh;  // row = 16 uint2
    int beg = g_off[n], end = g_off[n + 1];
    float dn = g_dinv[n];
    float sl = dn * dn;
    float4 acc;
    {
        uint2 raw = mh[(long)n * 16 + l];
        float2 a0 = __half22float2(*(const __half2*)&raw.x);
        float2 a1 = __half22float2(*(const __half2*)&raw.y);
        acc = make_float4(a0.x * sl, a0.y * sl, a1.x * sl, a1.y * sl);
    }
#pragma unroll 4
    for (int i = beg; i < end; i++) {
        int s = g_src[i];
        float cf = g_coef[i];
        uint2 raw = mh[(long)s * 16 + l];
        float2 v0 = __half22float2(*(const __half2*)&raw.x);
        float2 v1 = __half22float2(*(const __half2*)&raw.y);
        acc.x += cf * v0.x; acc.y += cf * v0.y;
        acc.z += cf * v1.x; acc.w += cf * v1.y;
    }
    int j = l * 4;
    acc.x = fmaxf(acc.x + __ldg(b + j + 0), 0.0f);
    acc.y = fmaxf(acc.y + __ldg(b + j + 1), 0.0f);
    acc.z = fmaxf(acc.z + __ldg(b + j + 2), 0.0f);
    acc.w = fmaxf(acc.w + __ldg(b + j + 3), 0.0f);
    ((float4*)outp)[n * 16 + l] = acc;
}

// ---------------------------------------------------------------------------
extern "C" void kernel_launch(void* const* d_in, const int* in_sizes, int n_in,
                              void* d_out, int out_size) {
    const float* x = (const float*)d_in[0];
    const void*  ei = d_in[1];
    const float* ew = (const float*)d_in[2];
    const float* W1 = (const float*)d_in[3];
    const float* b1 = (const float*)d_in[4];
    const float* W2 = (const float*)d_in[5];
    const float* b2 = (const float*)d_in[6];
    const float* W3 = (const float*)d_in[7];
    const float* b3 = (const float*)d_in[8];
    float* out = (float*)d_out;

    const int nB = (NN + 255) / 256;
    const int eB = (NE + 255) / 256;

    // --- dtype detect + normalization + CSR build ---
    k_detect_zero<<<nB, 256>>>((const int*)ei);
    k_deg_count<<<eB, 256>>>(ei, ew);
    k_scan1<<<SCAN_NB, SCAN_B>>>();
    k_scan23<<<nB, 256>>>();
    k_fill<<<eB, 256>>>(ei, ew);

    const int gemm_blocks = (NN + 63) / 64;           // 782
    const int g128_blocks = (NN * 32 + 255) / 256;
    const int g64_blocks  = (NN * 16 + 255) / 256;

    // --- layer 1 (128 -> 128) ---
    k_gemm_h<128, true><<<gemm_blocks, 256>>>(x, W1);
    k_gather128<false><<<g128_blocks, 256>>>(b1, nullptr);

    // --- layer 2 (128 -> 128) ---
    k_gemm_h<128, false><<<gemm_blocks, 256>>>(nullptr, W2);
    k_gather128<false><<<g128_blocks, 256>>>(b2, nullptr);

    // --- layer 3 (128 -> 64) ---
    k_gemm_h<64, false><<<gemm_blocks, 256>>>(nullptr, W3);
    k_gather64_out<<<g64_blocks, 256>>>(b3, out);
}

// round 13
// speedup vs baseline: 2.0283x; 1.0393x over previous
#include <cuda_runtime.h>
#include <cuda_fp16.h>
#include <cstdint>

#define NN 50000
#define NE 800000
#define SCAN_B 512
#define SCAN_NB ((NN + SCAN_B - 1) / SCAN_B)  // 98

// ---------------------------------------------------------------------------
// Scratch (__device__ globals). g_degcnt is zero at module load and restored
// to zero by k_scan1 each call (self-restoring invariant -> no zeroing pass).
// ALL symbol references happen in device code only (host passes no symbol
// addresses -- the R12 bug).
// ---------------------------------------------------------------------------
__device__ unsigned long long g_degcnt[NN];  // cnt bits[40..], weight 2^-32 fixed pt
__device__ float              g_dinv[NN];
__device__ int                g_off[NN + 1];
__device__ int                g_cursor[NN];
__device__ int                g_bsum[SCAN_NB];
__device__ __align__(8) uint2 g_edge[NE];    // (src, coef fp32 bits), sorted by dest
__device__ __align__(16) __half2 g_mA[NN * 64];  // message ping buffer
__device__ __align__(16) __half2 g_mB[NN * 64];  // message pong buffer

// ---------------------------------------------------------------------------
// fp16 MMA m16n8k16, fp32 accumulate
// ---------------------------------------------------------------------------
__device__ __forceinline__ void mma_f16(float4& d, uint32_t a0, uint32_t a1,
                                        uint32_t a2, uint32_t a3,
                                        uint32_t b0, uint32_t b1) {
    asm volatile(
        "mma.sync.aligned.m16n8k16.row.col.f32.f16.f16.f32 "
        "{%0,%1,%2,%3}, {%4,%5,%6,%7}, {%8,%9}, {%0,%1,%2,%3};"
        : "+f"(d.x), "+f"(d.y), "+f"(d.z), "+f"(d.w)
        : "r"(a0), "r"(a1), "r"(a2), "r"(a3), "r"(b0), "r"(b1));
}

// Per-block dtype detection: int64 edge data (ids < 2^31) has all-zero odd
// words; int32 has random ids there. 512 samples, L2-cached after block 0.
__device__ __forceinline__ int detect_is64(const int* __restrict__ ei32) {
    __shared__ int nz;
    if (threadIdx.x == 0) nz = 0;
    __syncthreads();
    for (int k = threadIdx.x; k < 512; k += blockDim.x)
        if (ei32[2 * k + 1] != 0) nz = 1;
    __syncthreads();
    return nz == 0;
}

__device__ __forceinline__ int load_idx(const void* ei, long i, int is64) {
    int v = is64 ? (int)((const long long*)ei)[i] : ((const int*)ei)[i];
    return min(max(v, 0), NN - 1);  // defensive clamp
}

// ---------------------------------------------------------------------------
// Normalization + CSR build
// ---------------------------------------------------------------------------
__global__ void k_deg_count(const void* __restrict__ ei, const float* __restrict__ ew) {
    int is64 = detect_is64((const int*)ei);
    int e = blockIdx.x * blockDim.x + threadIdx.x;
    if (e < NE) {
        int col = load_idx(ei, (long)NE + e, is64);
        unsigned long long v =
            (1ull << 40) | (unsigned long long)(ew[e] * 4294967296.0f);
        atomicAdd(&g_degcnt[col], v);
    }
}

// scan step 1 + dinv decode + degcnt restore-to-zero
__global__ void k_scan1() {
    __shared__ int s[SCAN_B];
    int tid = threadIdx.x;
    int i = blockIdx.x * SCAN_B + tid;
    int v = 0;
    if (i < NN) {
        unsigned long long dc = g_degcnt[i];
        g_degcnt[i] = 0ull;  // restore invariant for next call
        float deg = (float)(dc & 0xFFFFFFFFFFull) * 2.3283064365386963e-10f;
        g_dinv[i] = rsqrtf(deg + 1.0f);  // self-loop weight 1
        v = (int)(dc >> 40);
    }
    s[tid] = v;
    __syncthreads();
#pragma unroll
    for (int off = 1; off < SCAN_B; off <<= 1) {
        int t = (tid >= off) ? s[tid - off] : 0;
        __syncthreads();
        s[tid] += t;
        __syncthreads();
    }
    if (i < NN) g_off[i] = s[tid] - v;
    if (tid == SCAN_B - 1) g_bsum[blockIdx.x] = s[tid];
}

// fused scan2+scan3: every block re-scans the 98 block sums locally
__global__ void k_scan23() {
    __shared__ int s[128];
    __shared__ int pre[SCAN_NB];
    int tid = threadIdx.x;
    int v = 0;
    if (tid < 128) { v = (tid < SCAN_NB) ? g_bsum[tid] : 0; s[tid] = v; }
    __syncthreads();
#pragma unroll
    for (int off = 1; off < 128; off <<= 1) {
        int t = 0;
        if (tid < 128 && tid >= off) t = s[tid - off];
        __syncthreads();
        if (tid < 128) s[tid] += t;
        __syncthreads();
    }
    if (tid < SCAN_NB) pre[tid] = s[tid] - v;
    __syncthreads();
    int i = blockIdx.x * blockDim.x + tid;
    if (i < NN) {
        int o = g_off[i] + pre[i / SCAN_B];
        g_off[i] = o;
        g_cursor[i] = o;
    }
    if (i == 0) g_off[NN] = NE;
}

__global__ void k_fill(const void* __restrict__ ei, const float* __restrict__ ew) {
    int is64 = detect_is64((const int*)ei);
    int e = blockIdx.x * blockDim.x + threadIdx.x;
    if (e < NE) {
        int row = load_idx(ei, e, is64);
        int col = load_idx(ei, (long)NE + e, is64);
        int pos = atomicAdd(&g_cursor[col], 1);
        pos = min(max(pos, 0), NE - 1);
        float coef = g_dinv[row] * ew[e] * g_dinv[col];
        uint2 rec;
        rec.x = (uint32_t)row;
        rec.y = __float_as_uint(coef);
        g_edge[pos] = rec;  // one 8B scattered store
    }
}

// ---------------------------------------------------------------------------
// Layer-1 GEMM (x fp32 -> mA fp16): m = x @ W1^T. Proven R11 structure.
// Block 64 rows x 128 cols, 8 warps = 2 m-warps x 4 n-warps x two m16 subtiles.
// Writes g_mA by symbol name (device-side).
// ---------------------------------------------------------------------------
__global__ __launch_bounds__(256) void k_gemm1(const float* __restrict__ x,
                                               const float* __restrict__ W) {
    constexpr int D = 128, NT = D / 32;
    __shared__ __half2 Wh[D * 20];
    __shared__ __half2 hs2[64 * 20];

    const int tid = threadIdx.x;
    const int warp = tid >> 5, lane = tid & 31;
    const int wm = warp >> 2, wn = warp & 3;
    const int gid = lane >> 2, tig = lane & 3;
    const int row0 = blockIdx.x * 64;

    float4 acc[2][NT];
#pragma unroll
    for (int s = 0; s < 2; s++)
#pragma unroll
        for (int t = 0; t < NT; t++) acc[s][t] = make_float4(0.f, 0.f, 0.f, 0.f);

    for (int c = 0; c < 4; c++) {
        for (int idx = tid; idx < D * 16; idx += 256) {
            int n = idx >> 4, kk = idx & 15;
            float2 wv = *(const float2*)(W + n * 128 + c * 32 + kk * 2);
            Wh[n * 20 + kk] = __floats2half2_rn(wv.x, wv.y);
        }
        for (int idx = tid; idx < 512; idx += 256) {
            int r = idx >> 3, q = idx & 7;
            int gr = row0 + r;
            uint2 packed = make_uint2(0u, 0u);
            if (gr < NN) {
                float4 v = *(const float4*)(x + (long)gr * 128 + c * 32 + q * 4);
                __half2 p0 = __floats2half2_rn(v.x, v.y);
                __half2 p1 = __floats2half2_rn(v.z, v.w);
                packed.x = *(const uint32_t*)&p0;
                packed.y = *(const uint32_t*)&p1;
            }
            *(uint2*)(hs2 + r * 20 + q * 2) = packed;
        }
        __syncthreads();

        const uint32_t* whu = (const uint32_t*)Wh;
        const uint32_t* hsu = (const uint32_t*)hs2;
#pragma unroll
        for (int ks = 0; ks < 2; ks++) {
            const int kb = ks * 8;
            uint32_t a[2][4];
#pragma unroll
            for (int s = 0; s < 2; s++) {
                const int rb = wm * 32 + s * 16;
                a[s][0] = hsu[(rb + gid) * 20 + kb + tig];
                a[s][1] = hsu[(rb + gid + 8) * 20 + kb + tig];
                a[s][2] = hsu[(rb + gid) * 20 + kb + tig + 4];
                a[s][3] = hsu[(rb + gid + 8) * 20 + kb + tig + 4];
            }
#pragma unroll
            for (int t = 0; t < NT; t++) {
                int n = wn * (D / 4) + t * 8 + gid;
                uint32_t b0 = whu[n * 20 + kb + tig];
                uint32_t b1 = whu[n * 20 + kb + tig + 4];
                mma_f16(acc[0][t], a[0][0], a[0][1], a[0][2], a[0][3], b0, b1);
                mma_f16(acc[1][t], a[1][0], a[1][1], a[1][2], a[1][3], b0, b1);
            }
        }
        __syncthreads();
    }

#pragma unroll
    for (int s = 0; s < 2; s++) {
        const int r0 = row0 + wm * 32 + s * 16 + gid;
        const int r1 = r0 + 8;
#pragma unroll
        for (int t = 0; t < NT; t++) {
            int cidx = wn * (D / 8) + t * 4 + tig;
            if (r0 < NN) g_mA[(long)r0 * 64 + cidx] = __floats2half2_rn(acc[s][t].x, acc[s][t].y);
            if (r1 < NN) g_mA[(long)r1 * 64 + cidx] = __floats2half2_rn(acc[s][t].z, acc[s][t].w);
        }
    }
}

// ---------------------------------------------------------------------------
// Fused gather+GEMM layer. A_TO_B=true: read g_mA, write g_mB; else reverse.
// Input m always has 128 cols; D = output dim. Gather (+self-loop+bias+ReLU)
// builds h for this block's 64 nodes in SMEM only; then m_out = h @ W^T.
// Buffers are selected BY SYMBOL in device code (no host symbol addresses).
// ---------------------------------------------------------------------------
template <int D, bool A_TO_B>
__global__ __launch_bounds__(256) void k_fused(const float* __restrict__ bprev,
                                               const float* __restrict__ W) {
    constexpr int NT = D / 32;
    constexpr int HS = 68;  // h row stride in half2 (64 + pad 4)
    __shared__ __half2 Wh[D * 20];
    __shared__ __half2 hs2[64 * HS];

    const __half2* min_ = A_TO_B ? g_mA : g_mB;
    __half2*       mout = A_TO_B ? g_mB : g_mA;

    const int tid = threadIdx.x;
    const int warp = tid >> 5, lane = tid & 31;
    const int row0 = blockIdx.x * 64;

    // ---- gather phase: produce h rows for this block ----
    {
        const uint2* mh = (const uint2*)min_;  // input row = 32 uint2 (128 cols fp16)
        float bx = __ldg(bprev + lane * 4 + 0);
        float by = __ldg(bprev + lane * 4 + 1);
        float bz = __ldg(bprev + lane * 4 + 2);
        float bw = __ldg(bprev + lane * 4 + 3);
#pragma unroll
        for (int j = 0; j < 8; j++) {
            int r = warp * 8 + j;
            int n = row0 + r;
            uint2 packed = make_uint2(0u, 0u);
            if (n < NN) {
                int beg = g_off[n], end = g_off[n + 1];
                float dn = g_dinv[n];
                float sl = dn * dn;
                float4 acc;
                {
                    uint2 raw = mh[(long)n * 32 + lane];
                    float2 a0 = __half22float2(*(const __half2*)&raw.x);
                    float2 a1 = __half22float2(*(const __half2*)&raw.y);
                    acc = make_float4(a0.x * sl, a0.y * sl, a1.x * sl, a1.y * sl);
                }
                for (int i = beg; i < end; i++) {
                    uint2 er = g_edge[i];
                    float cf = __uint_as_float(er.y);
                    uint2 raw = mh[(long)er.x * 32 + lane];
                    float2 v0 = __half22float2(*(const __half2*)&raw.x);
                    float2 v1 = __half22float2(*(const __half2*)&raw.y);
                    acc.x += cf * v0.x; acc.y += cf * v0.y;
                    acc.z += cf * v1.x; acc.w += cf * v1.y;
                }
                acc.x = fmaxf(acc.x + bx, 0.0f);
                acc.y = fmaxf(acc.y + by, 0.0f);
                acc.z = fmaxf(acc.z + bz, 0.0f);
                acc.w = fmaxf(acc.w + bw, 0.0f);
                __half2 p0 = __floats2half2_rn(acc.x, acc.y);
                __half2 p1 = __floats2half2_rn(acc.z, acc.w);
                packed.x = *(const uint32_t*)&p0;
                packed.y = *(const uint32_t*)&p1;
            }
            *(uint2*)(hs2 + r * HS + lane * 2) = packed;
        }
    }
    __syncthreads();

    // ---- GEMM phase: m_out = h @ W^T from SMEM h ----
    const int wm = warp >> 2, wn = warp & 3;
    const int gid = lane >> 2, tig = lane & 3;

    float4 acc[2][NT];
#pragma unroll
    for (int s = 0; s < 2; s++)
#pragma unroll
        for (int t = 0; t < NT; t++) acc[s][t] = make_float4(0.f, 0.f, 0.f, 0.f);

    const uint32_t* hsu = (const uint32_t*)hs2;
    for (int c = 0; c < 4; c++) {
        for (int idx = tid; idx < D * 16; idx += 256) {
            int n = idx >> 4, kk = idx & 15;
            float2 wv = *(const float2*)(W + n * 128 + c * 32 + kk * 2);
            Wh[n * 20 + kk] = __floats2half2_rn(wv.x, wv.y);
        }
        __syncthreads();

        const uint32_t* whu = (const uint32_t*)Wh;
#pragma unroll
        for (int ks = 0; ks < 2; ks++) {
            const int kb = c * 16 + ks * 8;
            uint32_t a[2][4];
#pragma unroll
            for (int s = 0; s < 2; s++) {
                const int rb = wm * 32 + s * 16;
                a[s][0] = hsu[(rb + gid) * HS + kb + tig];
                a[s][1] = hsu[(rb + gid + 8) * HS + kb + tig];
                a[s][2] = hsu[(rb + gid) * HS + kb + tig + 4];
                a[s][3] = hsu[(rb + gid + 8) * HS + kb + tig + 4];
            }
#pragma unroll
            for (int t = 0; t < NT; t++) {
                int n = wn * (D / 4) + t * 8 + gid;
                uint32_t b0 = whu[n * 20 + ks * 8 + tig];
                uint32_t b1 = whu[n * 20 + ks * 8 + tig + 4];
                mma_f16(acc[0][t], a[0][0], a[0][1], a[0][2], a[0][3], b0, b1);
                mma_f16(acc[1][t], a[1][0], a[1][1], a[1][2], a[1][3], b0, b1);
            }
        }
        __syncthreads();
    }

#pragma unroll
    for (int s = 0; s < 2; s++) {
        const int r0 = row0 + wm * 32 + s * 16 + gid;
        const int r1 = r0 + 8;
#pragma unroll
        for (int t = 0; t < NT; t++) {
            int cidx = wn * (D / 8) + t * 4 + tig;
            if (r0 < NN) mout[(long)r0 * (D / 2) + cidx] = __floats2half2_rn(acc[s][t].x, acc[s][t].y);
            if (r1 < NN) mout[(long)r1 * (D / 2) + cidx] = __floats2half2_rn(acc[s][t].z, acc[s][t].w);
        }
    }
}

// ---------------------------------------------------------------------------
// Final gather: g_mA (fp16, 64 cols) -> fp32 out, fused bias + ReLU.
// Half-warp per node, packed edge records.
// ---------------------------------------------------------------------------
__global__ __launch_bounds__(256) void k_gather_out(const float* __restrict__ b,
                                                    float* __restrict__ outp) {
    int gw = (blockIdx.x * blockDim.x + threadIdx.x) >> 5;
    int lane = threadIdx.x & 31;
    int n = gw * 2 + (lane >> 4);
    int l = lane & 15;
    if (n >= NN) return;
    const uint2* mh = (const uint2*)g_mA;  // row = 16 uint2 (64 cols fp16)
    int beg = g_off[n], end = g_off[n + 1];
    float dn = g_dinv[n];
    float sl = dn * dn;
    float4 acc;
    {
        uint2 raw = mh[(long)n * 16 + l];
        float2 a0 = __half22float2(*(const __half2*)&raw.x);
        float2 a1 = __half22float2(*(const __half2*)&raw.y);
        acc = make_float4(a0.x * sl, a0.y * sl, a1.x * sl, a1.y * sl);
    }
#pragma unroll 4
    for (int i = beg; i < end; i++) {
        uint2 er = g_edge[i];
        float cf = __uint_as_float(er.y);
        uint2 raw = mh[(long)er.x * 16 + l];
        float2 v0 = __half22float2(*(const __half2*)&raw.x);
        float2 v1 = __half22float2(*(const __half2*)&raw.y);
        acc.x += cf * v0.x; acc.y += cf * v0.y;
        acc.z += cf * v1.x; acc.w += cf * v1.y;
    }
    int j = l * 4;
    acc.x = fmaxf(acc.x + __ldg(b + j + 0), 0.0f);
    acc.y = fmaxf(acc.y + __ldg(b + j + 1), 0.0f);
    acc.z = fmaxf(acc.z + __ldg(b + j + 2), 0.0f);
    acc.w = fmaxf(acc.w + __ldg(b + j + 3), 0.0f);
    ((float4*)outp)[n * 16 + l] = acc;
}

// ---------------------------------------------------------------------------
extern "C" void kernel_launch(void* const* d_in, const int* in_sizes, int n_in,
                              void* d_out, int out_size) {
    const float* x = (const float*)d_in[0];
    const void*  ei = d_in[1];
    const float* ew = (const float*)d_in[2];
    const float* W1 = (const float*)d_in[3];
    const float* b1 = (const float*)d_in[4];
    const float* W2 = (const float*)d_in[5];
    const float* b2 = (const float*)d_in[6];
    const float* W3 = (const float*)d_in[7];
    const float* b3 = (const float*)d_in[8];
    float* out = (float*)d_out;

    const int eB = (NE + 255) / 256;
    const int nB = (NN + 255) / 256;
    const int gemm_blocks = (NN + 63) / 64;           // 782
    const int gout_blocks = (NN * 16 + 255) / 256;    // 3125

    // --- preprocess: deg/cnt -> scan -> CSR fill (degcnt self-restoring) ---
    k_deg_count<<<eB, 256>>>(ei, ew);
    k_scan1<<<SCAN_NB, SCAN_B>>>();
    k_scan23<<<nB, 256>>>();
    k_fill<<<eB, 256>>>(ei, ew);

    // --- layers: gemm1 -> fused(gather+gemm) x2 -> gather_out ---
    k_gemm1<<<gemm_blocks, 256>>>(x, W1);                  // x @ W1 -> mA
    k_fused<128, true><<<gemm_blocks, 256>>>(b1, W2);      // agg(mA)+b1,relu @ W2 -> mB
    k_fused<64, false><<<gemm_blocks, 256>>>(b2, W3);      // agg(mB)+b2,relu @ W3 -> mA
    k_gather_out<<<gout_blocks, 256>>>(b3, out);           // agg(mA)+b3,relu -> out
}